// round 12
// baseline (speedup 1.0000x reference)
#include <cuda_runtime.h>
#include <cuda_bf16.h>
#include <cuda_fp16.h>
#include <math.h>
#include <stdint.h>

// Problem constants
#define BB 2
#define LL 2048
#define DMODEL 1024
#define NH 16
#define DK 64
#define MROWS (BB * LL)          // 4096
#define MASK_W (LL / 32)         // 64 words per row
#define MASK_WORDS (LL * MASK_W)

// ---------------------------------------------------------------------------
// Device scratch (no allocations allowed)
// ---------------------------------------------------------------------------
__device__ __half g_in_q[MROWS * DMODEL], g_in_k[MROWS * DMODEL], g_in_v[MROWS * DMODEL];
__device__ __half g_w_qh[DMODEL * DMODEL], g_w_ql[DMODEL * DMODEL];
__device__ __half g_w_kh[DMODEL * DMODEL], g_w_kl[DMODEL * DMODEL];
__device__ __half g_w_vh[DMODEL * DMODEL], g_w_vl[DMODEL * DMODEL];
__device__ __half g_w_oh[DMODEL * DMODEL], g_w_ol[DMODEL * DMODEL];
__device__ __nv_bfloat16 g_Qh[MROWS * DMODEL], g_Ql[MROWS * DMODEL];   // [b,h,l,d] bf16
__device__ __nv_bfloat16 g_Kh[MROWS * DMODEL], g_Kl[MROWS * DMODEL];   // [b,h,l,d] bf16
__device__ __half g_Vfh[MROWS * DMODEL], g_Vfl[MROWS * DMODEL];        // [b,h,l,d] fp16 hi/lo
__device__ __half g_Cf[MROWS * DMODEL];                                // [b,l,dmodel] fp16
__device__ unsigned int g_maskbits[MASK_WORDS];

// ---------------------------------------------------------------------------
// PTX helpers (portable PTX only: mma.sync / ldmatrix / cp.async)
// ---------------------------------------------------------------------------
__device__ __forceinline__ uint32_t smem_u32(const void* p) {
    uint32_t a;
    asm("{ .reg .u64 t; cvta.to.shared.u64 t, %1; cvt.u32.u64 %0, t; }" : "=r"(a) : "l"(p));
    return a;
}

#define CP_ASYNC16(dst, src) \
    asm volatile("cp.async.cg.shared.global [%0], [%1], 16;" :: "r"(dst), "l"(src))
#define CP_COMMIT() asm volatile("cp.async.commit_group;" ::: "memory")
#define CP_WAIT1()  asm volatile("cp.async.wait_group 1;" ::: "memory")

#define LDSM_X4(r0, r1, r2, r3, addr) \
    asm volatile("ldmatrix.sync.aligned.m8n8.x4.shared.b16 {%0,%1,%2,%3}, [%4];" \
        : "=r"(r0), "=r"(r1), "=r"(r2), "=r"(r3) : "r"(addr))
#define LDSM_X4_T(r0, r1, r2, r3, addr) \
    asm volatile("ldmatrix.sync.aligned.m8n8.x4.trans.shared.b16 {%0,%1,%2,%3}, [%4];" \
        : "=r"(r0), "=r"(r1), "=r"(r2), "=r"(r3) : "r"(addr))

__device__ __forceinline__ void mma_bf16(float* c, uint32_t a0, uint32_t a1, uint32_t a2, uint32_t a3,
                                         uint32_t b0, uint32_t b1) {
    asm volatile("mma.sync.aligned.m16n8k16.row.col.f32.bf16.bf16.f32 "
        "{%0,%1,%2,%3}, {%4,%5,%6,%7}, {%8,%9}, {%0,%1,%2,%3};"
        : "+f"(c[0]), "+f"(c[1]), "+f"(c[2]), "+f"(c[3])
        : "r"(a0), "r"(a1), "r"(a2), "r"(a3), "r"(b0), "r"(b1));
}
__device__ __forceinline__ void mma_f16(float* c, uint32_t a0, uint32_t a1, uint32_t a2, uint32_t a3,
                                        uint32_t b0, uint32_t b1) {
    asm volatile("mma.sync.aligned.m16n8k16.row.col.f32.f16.f16.f32 "
        "{%0,%1,%2,%3}, {%4,%5,%6,%7}, {%8,%9}, {%0,%1,%2,%3};"
        : "+f"(c[0]), "+f"(c[1]), "+f"(c[2]), "+f"(c[3])
        : "r"(a0), "r"(a1), "r"(a2), "r"(a3), "r"(b0), "r"(b1));
}

__device__ __forceinline__ void split2(float x, __nv_bfloat16& h, __nv_bfloat16& l) {
    h = __float2bfloat16(x);
    l = __float2bfloat16(x - __bfloat162float(h));
}
__device__ __forceinline__ void split2h(float x, __half& h, __half& l) {
    h = __float2half_rn(x);
    l = __float2half_rn(x - __half2float(h));
}
__device__ __forceinline__ uint32_t pack_h2(__half e0, __half e1) {
    __half2 t; t.x = e0; t.y = e1;
    return *(uint32_t*)&t;
}
__device__ __forceinline__ void store_bf2(__nv_bfloat16* p, __nv_bfloat16 e0, __nv_bfloat16 e1) {
    __nv_bfloat162 t; t.x = e0; t.y = e1;
    *(__nv_bfloat162*)p = t;
}
__device__ __forceinline__ void store_h2(__half* p, __half e0, __half e1) {
    __half2 t; t.x = e0; t.y = e1;
    *(__half2*)p = t;
}

// ---------------------------------------------------------------------------
// Mask -> bitmask (dtype sniffing: u8 / i32 / f32)
// ---------------------------------------------------------------------------
__global__ void convert_mask_bits(const void* __restrict__ mask_in) {
    const unsigned int* w = (const unsigned int*)mask_in;
    bool all_i32 = true, all_f32 = true;
    #pragma unroll
    for (int i = 0; i < 64; i++) {
        unsigned int v = w[i];
        if (v > 1u) all_i32 = false;
        if (v != 0u && v != 0x3F800000u) all_f32 = false;
    }
    int idx = blockIdx.x * blockDim.x + threadIdx.x;   // word index
    if (idx >= MASK_WORDS) return;
    size_t base = (size_t)idx * 32;
    uint32_t bits = 0;
    if (all_i32 || all_f32) {
        const uint4* p = (const uint4*)((const unsigned int*)mask_in + base);
        #pragma unroll
        for (int g = 0; g < 8; g++) {
            uint4 v = p[g];
            bits |= (v.x != 0u ? 1u : 0u) << (g * 4 + 0);
            bits |= (v.y != 0u ? 1u : 0u) << (g * 4 + 1);
            bits |= (v.z != 0u ? 1u : 0u) << (g * 4 + 2);
            bits |= (v.w != 0u ? 1u : 0u) << (g * 4 + 3);
        }
    } else {
        const uchar4* p = (const uchar4*)((const unsigned char*)mask_in + base);
        #pragma unroll
        for (int g = 0; g < 8; g++) {
            uchar4 v = p[g];
            bits |= (v.x ? 1u : 0u) << (g * 4 + 0);
            bits |= (v.y ? 1u : 0u) << (g * 4 + 1);
            bits |= (v.z ? 1u : 0u) << (g * 4 + 2);
            bits |= (v.w ? 1u : 0u) << (g * 4 + 3);
        }
    }
    g_maskbits[idx] = bits;
}

// ---------------------------------------------------------------------------
// Fused input convert to single fp16 (q/k/v chosen by blockIdx.y)
// ---------------------------------------------------------------------------
__global__ void conv3_kernel(const float4* __restrict__ q, const float4* __restrict__ k,
                             const float4* __restrict__ v,
                             __half2* __restrict__ oq, __half2* __restrict__ ok,
                             __half2* __restrict__ ov, int n4) {
    const float4* in = (blockIdx.y == 0) ? q : (blockIdx.y == 1) ? k : v;
    __half2* out = (blockIdx.y == 0) ? oq : (blockIdx.y == 1) ? ok : ov;
    int i = blockIdx.x * blockDim.x + threadIdx.x;
    if (i >= n4) return;
    float4 vv = in[i];
    __half2 a, b;
    a.x = __float2half_rn(vv.x); a.y = __float2half_rn(vv.y);
    b.x = __float2half_rn(vv.z); b.y = __float2half_rn(vv.w);
    out[i * 2] = a;
    out[i * 2 + 1] = b;
}

// Fused weight transpose+split to fp16 hi/lo (4 weights by blockIdx.z)
__global__ void transpose_split4_kernel(
    const float* __restrict__ wq, const float* __restrict__ wk,
    const float* __restrict__ wv, const float* __restrict__ wo,
    __half* __restrict__ qh, __half* __restrict__ ql,
    __half* __restrict__ kh, __half* __restrict__ kl,
    __half* __restrict__ vh, __half* __restrict__ vl,
    __half* __restrict__ oh, __half* __restrict__ ol) {
    const float* in = (blockIdx.z == 0) ? wq : (blockIdx.z == 1) ? wk : (blockIdx.z == 2) ? wv : wo;
    __half* hi = (blockIdx.z == 0) ? qh : (blockIdx.z == 1) ? kh : (blockIdx.z == 2) ? vh : oh;
    __half* lo = (blockIdx.z == 0) ? ql : (blockIdx.z == 1) ? kl : (blockIdx.z == 2) ? vl : ol;
    __shared__ float t[32][33];
    int k0 = blockIdx.y * 32, n0 = blockIdx.x * 32;
    t[threadIdx.y][threadIdx.x] = in[(size_t)(k0 + threadIdx.y) * DMODEL + n0 + threadIdx.x];
    __syncthreads();
    float v = t[threadIdx.x][threadIdx.y];
    int n = n0 + threadIdx.y, k = k0 + threadIdx.x;
    __half h, l;
    split2h(v, h, l);
    hi[(size_t)n * DMODEL + k] = h;
    lo[(size_t)n * DMODEL + k] = l;
}

// ---------------------------------------------------------------------------
// GEMM (fp16, 2-pass): C[m][n] = sum_k A[m,k]*(Wh+Wl)[n,k] + bias[n]
// A is single fp16; W is fp16 hi/lo. 3-STAGE cp.async ring.
// mode 0: fp32 out; 1: bf16 hi/lo [b,h,l,d]; 2: fp16 hi/lo [b,h,l,d].
// ---------------------------------------------------------------------------
#define G_STRIDE 80
#define G_MAT    10240          // 128*80
#define G_STAGE  30720          // 3 mats
#define GEMM_SMEM (3 * G_STAGE) // 92160

struct GArgs {
    const __half *A[3], *Bh[3], *Bl[3];
    const float* bias[3];
    float* outF[3];
    __nv_bfloat16 *oh[3], *ol[3];
    __half *ohf[3], *olf[3];
    int mode[3];
};

__global__ __launch_bounds__(256, 2) void mma_gemm(GArgs ga)
{
    extern __shared__ char smem[];
    const uint32_t sb = smem_u32(smem);
    const int z = blockIdx.z;
    const __half* __restrict__ A  = ga.A[z];
    const __half* __restrict__ Bh = ga.Bh[z];
    const __half* __restrict__ Bl = ga.Bl[z];
    const float* __restrict__ bias = ga.bias[z];
    const int mode = ga.mode[z];

    const int tid = threadIdx.x, wid = tid >> 5, lane = tid & 31;
    const int bm = blockIdx.y * 128, bn = blockIdx.x * 128;
    const int warpM = (wid >> 1) * 32, warpN = (wid & 1) * 64;

    float acc[2][8][4];
    #pragma unroll
    for (int i = 0; i < 2; i++)
        #pragma unroll
        for (int j = 0; j < 8; j++)
            #pragma unroll
            for (int r = 0; r < 4; r++) acc[i][j][r] = 0.0f;

    const __half* srcs[3] = {A, Bh, Bl};

    // prologue: tiles 0 and 1 -> stages 0 and 1 (separate commit groups)
    #pragma unroll
    for (int t = 0; t < 2; t++) {
        const uint32_t stg = sb + t * G_STAGE;
        const int k0 = t * 32;
        #pragma unroll
        for (int i = 0; i < 6; i++) {
            int c = tid + i * 256;
            int mat = c >> 9, r = (c >> 2) & 127, seg = c & 3;
            uint32_t dst = stg + mat * G_MAT + r * G_STRIDE + seg * 16;
            int row = (mat < 1) ? (bm + r) : (bn + r);
            CP_ASYNC16(dst, srcs[mat] + (size_t)row * DMODEL + k0 + seg * 8);
        }
        CP_COMMIT();
    }

    int st = 0;          // stage of current tile
    for (int it = 0; it < 32; it++) {
        CP_WAIT1();       // tile `it` resident (tile it+1 may still fly)
        __syncthreads();  // all warps done computing tile it-1 (stage being refilled)
        {
            int pst = st + 2; if (pst >= 3) pst -= 3;
            if (it + 2 < 32) {
                const int k0 = (it + 2) * 32;
                const uint32_t stg = sb + pst * G_STAGE;
                #pragma unroll
                for (int i = 0; i < 6; i++) {
                    int c = tid + i * 256;
                    int mat = c >> 9, r = (c >> 2) & 127, seg = c & 3;
                    uint32_t dst = stg + mat * G_MAT + r * G_STRIDE + seg * 16;
                    int row = (mat < 1) ? (bm + r) : (bn + r);
                    CP_ASYNC16(dst, srcs[mat] + (size_t)row * DMODEL + k0 + seg * 8);
                }
            }
            CP_COMMIT();  // always commit (possibly empty) to keep group count uniform
        }

        const uint32_t stg = sb + st * G_STAGE;
        const uint32_t aRow = warpM + (lane & 15);
        #pragma unroll
        for (int ks = 0; ks < 2; ks++) {
            const uint32_t kOffA = (ks * 16 + 8 * (lane >> 4)) * 2;
            const uint32_t kOffB = (ks * 16 + 8 * ((lane >> 3) & 1)) * 2;
            uint32_t ah[2][4];
            #pragma unroll
            for (int mi = 0; mi < 2; mi++) {
                uint32_t ad = stg + (aRow + mi * 16) * G_STRIDE + kOffA;
                LDSM_X4(ah[mi][0], ah[mi][1], ah[mi][2], ah[mi][3], ad);
            }
            #pragma unroll
            for (int nj = 0; nj < 8; nj += 2) {
                uint32_t bd = stg + G_MAT
                            + (warpN + (nj + (lane >> 4)) * 8 + (lane & 7)) * G_STRIDE + kOffB;
                uint32_t bh0, bh1, bh2, bh3, bl0, bl1, bl2, bl3;
                LDSM_X4(bh0, bh1, bh2, bh3, bd);
                LDSM_X4(bl0, bl1, bl2, bl3, bd + G_MAT);
                #pragma unroll
                for (int mi = 0; mi < 2; mi++) {
                    mma_f16(acc[mi][nj], ah[mi][0], ah[mi][1], ah[mi][2], ah[mi][3], bh0, bh1);
                    mma_f16(acc[mi][nj], ah[mi][0], ah[mi][1], ah[mi][2], ah[mi][3], bl0, bl1);
                    mma_f16(acc[mi][nj + 1], ah[mi][0], ah[mi][1], ah[mi][2], ah[mi][3], bh2, bh3);
                    mma_f16(acc[mi][nj + 1], ah[mi][0], ah[mi][1], ah[mi][2], ah[mi][3], bl2, bl3);
                }
            }
        }
        st++; if (st >= 3) st -= 3;
    }

    // epilogue
    #pragma unroll
    for (int mi = 0; mi < 2; mi++) {
        #pragma unroll
        for (int nj = 0; nj < 8; nj++) {
            int n = bn + warpN + nj * 8 + 2 * (lane & 3);
            float bias0 = bias[n], bias1 = bias[n + 1];
            #pragma unroll
            for (int half = 0; half < 2; half++) {
                int m = bm + warpM + mi * 16 + (lane >> 2) + half * 8;
                float v0 = acc[mi][nj][half * 2 + 0] + bias0;
                float v1 = acc[mi][nj][half * 2 + 1] + bias1;
                if (mode == 0) {
                    float2 o; o.x = v0; o.y = v1;
                    *(float2*)&ga.outF[z][(size_t)m * DMODEL + n] = o;
                } else {
                    int b = m >> 11, l = m & 2047;
                    int h = n >> 6, d = n & 63;
                    size_t idx = (((size_t)(b * NH + h)) * LL + l) * DK + d;
                    if (mode == 1) {
                        __nv_bfloat16 h0, h1, l0, l1;
                        split2(v0, h0, l0); split2(v1, h1, l1);
                        store_bf2(&ga.oh[z][idx], h0, h1);
                        store_bf2(&ga.ol[z][idx], l0, l1);
                    } else {
                        __half h0, h1, l0, l1;
                        split2h(v0, h0, l0); split2h(v1, h1, l1);
                        store_h2(&ga.ohf[z][idx], h0, h1);
                        store_h2(&ga.olf[z][idx], l0, l1);
                    }
                }
            }
        }
    }
}

// ---------------------------------------------------------------------------
// Flash attention, ONLINE softmax, 3-STAGE cp.async ring.
// CTA: 128 queries x one (b,h); 32 key tiles of 64; 8 warps, warp = 16 queries.
// S = bf16 3-pass. P = single fp16 (p = exp(s - m) <= 1).
// P·V = fp16 2-pass (V hi/lo fp16) via mma_f16 + ldmatrix.trans.
// ---------------------------------------------------------------------------
#define A_KSTRIDE 144           // 64 elems * 2B + 16 pad
#define A_KMAT    9216          // 64*144
#define A_VOFF    18432         // 2*A_KMAT (V hi/lo follow K hi/lo)
#define A_STAGE   36864         // 4 mats * 9216
#define ATTN_SMEM (3 * A_STAGE) // 110592

__global__ __launch_bounds__(256, 2) void attn_mma(
    const __nv_bfloat16* __restrict__ Qh, const __nv_bfloat16* __restrict__ Ql,
    const __nv_bfloat16* __restrict__ Kh, const __nv_bfloat16* __restrict__ Kl,
    const __half* __restrict__ Vh, const __half* __restrict__ Vl,
    __half* __restrict__ Cf)
{
    extern __shared__ char smem[];
    const uint32_t sb = smem_u32(smem);
    const int tid = threadIdx.x, wid = tid >> 5, lane = tid & 31;
    const int bh = blockIdx.y, q0 = blockIdx.x * 128;
    const int warpM = wid * 16;

    const __nv_bfloat16* qbh = Qh + (size_t)bh * LL * DK;
    const __nv_bfloat16* qbl = Ql + (size_t)bh * LL * DK;
    const __nv_bfloat16* srcs[4] = {
        Kh + (size_t)bh * LL * DK, Kl + (size_t)bh * LL * DK,
        (const __nv_bfloat16*)(Vh + (size_t)bh * LL * DK),
        (const __nv_bfloat16*)(Vl + (size_t)bh * LL * DK)};

    // ---- Q preload into smem (stages 0-1 area), extract fragments, reuse ----
    #pragma unroll
    for (int i = 0; i < 8; i++) {
        int c = tid + i * 256;                 // 2048 chunks: 2 mats x 128 rows x 8 segs
        int mat = c >> 10, r = (c >> 3) & 127, seg = c & 7;
        const __nv_bfloat16* src = (mat ? qbl : qbh) + (size_t)(q0 + r) * DK + seg * 8;
        *(uint4*)(smem + mat * 18432 + r * A_KSTRIDE + seg * 16) = *(const uint4*)src;
    }
    __syncthreads();
    uint32_t qh[4][4], ql[4][4];
    {
        const uint32_t aRow = warpM + (lane & 15);
        #pragma unroll
        for (int ks = 0; ks < 4; ks++) {
            uint32_t ad = sb + aRow * A_KSTRIDE + (ks * 16 + 8 * (lane >> 4)) * 2;
            LDSM_X4(qh[ks][0], qh[ks][1], qh[ks][2], qh[ks][3], ad);
            LDSM_X4(ql[ks][0], ql[ks][1], ql[ks][2], ql[ks][3], ad + 18432);
        }
    }
    __syncthreads();

    // ---- K/V prologue: tiles 0,1 -> stages 0,1 ----
    #pragma unroll
    for (int t = 0; t < 2; t++) {
        const uint32_t stg = sb + t * A_STAGE;
        const int kbase = t * 64;
        #pragma unroll
        for (int i = 0; i < 8; i++) {
            int c = tid + i * 256;
            int mat = c >> 9, r = (c >> 3) & 63, seg = c & 7;
            uint32_t dst = stg + mat * A_KMAT + r * A_KSTRIDE + seg * 16;
            CP_ASYNC16(dst, srcs[mat] + (size_t)(kbase + r) * DK + seg * 8);
        }
        CP_COMMIT();
    }

    float Oacc[8][4];
    #pragma unroll
    for (int j = 0; j < 8; j++)
        #pragma unroll
        for (int r = 0; r < 4; r++) Oacc[j][r] = 0.0f;
    float rowsum0 = 0.0f, rowsum1 = 0.0f;
    float m0 = -INFINITY, m1 = -INFINITY;

    const int row0 = q0 + warpM + (lane >> 2);
    const int dc = 2 * (lane & 3);

    int st = 0;
    for (int kt = 0; kt < 32; kt++) {
        // mask bits for this tile (independent of smem; overlap with wait)
        uint32_t mw0[2], mw1[2];
        #pragma unroll
        for (int w = 0; w < 2; w++) {
            mw0[w] = g_maskbits[(size_t)row0 * MASK_W + kt * 2 + w];
            mw1[w] = g_maskbits[(size_t)(row0 + 8) * MASK_W + kt * 2 + w];
        }

        CP_WAIT1();
        __syncthreads();
        {
            int pst = st + 2; if (pst >= 3) pst -= 3;
            if (kt + 2 < 32) {
                const int kbase = (kt + 2) * 64;
                const uint32_t stg = sb + pst * A_STAGE;
                #pragma unroll
                for (int i = 0; i < 8; i++) {
                    int c = tid + i * 256;
                    int mat = c >> 9, r = (c >> 3) & 63, seg = c & 7;
                    uint32_t dst = stg + mat * A_KMAT + r * A_KSTRIDE + seg * 16;
                    CP_ASYNC16(dst, srcs[mat] + (size_t)(kbase + r) * DK + seg * 8);
                }
            }
            CP_COMMIT();
        }

        const uint32_t stg = sb + st * A_STAGE;

        // ---- S = Q K^T (bf16 3-pass) ----
        float Sacc[8][4];
        #pragma unroll
        for (int j = 0; j < 8; j++)
            #pragma unroll
            for (int r = 0; r < 4; r++) Sacc[j][r] = 0.0f;

        #pragma unroll
        for (int ks = 0; ks < 4; ks++) {
            const uint32_t kOffB = (ks * 16 + 8 * ((lane >> 3) & 1)) * 2;
            #pragma unroll
            for (int j = 0; j < 8; j += 2) {
                uint32_t bd = stg + ((j + (lane >> 4)) * 8 + (lane & 7)) * A_KSTRIDE + kOffB;
                uint32_t bh0, bh1, bh2, bh3, bl0, bl1, bl2, bl3;
                LDSM_X4(bh0, bh1, bh2, bh3, bd);
                LDSM_X4(bl0, bl1, bl2, bl3, bd + A_KMAT);
                mma_bf16(Sacc[j], qh[ks][0], qh[ks][1], qh[ks][2], qh[ks][3], bh0, bh1);
                mma_bf16(Sacc[j], qh[ks][0], qh[ks][1], qh[ks][2], qh[ks][3], bl0, bl1);
                mma_bf16(Sacc[j], ql[ks][0], ql[ks][1], ql[ks][2], ql[ks][3], bh0, bh1);
                mma_bf16(Sacc[j + 1], qh[ks][0], qh[ks][1], qh[ks][2], qh[ks][3], bh2, bh3);
                mma_bf16(Sacc[j + 1], qh[ks][0], qh[ks][1], qh[ks][2], qh[ks][3], bl2, bl3);
                mma_bf16(Sacc[j + 1], ql[ks][0], ql[ks][1], ql[ks][2], ql[ks][3], bh2, bh3);
            }
        }

        // ---- apply mask (s -> -inf) + tile row max ----
        float tmax0 = -INFINITY, tmax1 = -INFINITY;
        #pragma unroll
        for (int j = 0; j < 8; j++) {
            const int sh = (j & 3) * 8 + dc;
            uint32_t b0 = (mw0[j >> 2] >> sh) & 3u;
            uint32_t b1 = (mw1[j >> 2] >> sh) & 3u;
            if (b0 & 1u) Sacc[j][0] = -INFINITY;
            if (b0 & 2u) Sacc[j][1] = -INFINITY;
            if (b1 & 1u) Sacc[j][2] = -INFINITY;
            if (b1 & 2u) Sacc[j][3] = -INFINITY;
            tmax0 = fmaxf(tmax0, fmaxf(Sacc[j][0], Sacc[j][1]));
            tmax1 = fmaxf(tmax1, fmaxf(Sacc[j][2], Sacc[j][3]));
        }
        tmax0 = fmaxf(tmax0, __shfl_xor_sync(0xFFFFFFFFu, tmax0, 1));
        tmax0 = fmaxf(tmax0, __shfl_xor_sync(0xFFFFFFFFu, tmax0, 2));
        tmax1 = fmaxf(tmax1, __shfl_xor_sync(0xFFFFFFFFu, tmax1, 1));
        tmax1 = fmaxf(tmax1, __shfl_xor_sync(0xFFFFFFFFu, tmax1, 2));
        if (tmax0 > m0) {
            float sc = __expf(m0 - tmax0);   // m0=-inf -> 0; Oacc/rowsum were 0
            rowsum0 *= sc;
            #pragma unroll
            for (int dj = 0; dj < 8; dj++) { Oacc[dj][0] *= sc; Oacc[dj][1] *= sc; }
            m0 = tmax0;
        }
        if (tmax1 > m1) {
            float sc = __expf(m1 - tmax1);
            rowsum1 *= sc;
            #pragma unroll
            for (int dj = 0; dj < 8; dj++) { Oacc[dj][2] *= sc; Oacc[dj][3] *= sc; }
            m1 = tmax1;
        }
        const float mm0 = (m0 == -INFINITY) ? 0.0f : m0;
        const float mm1 = (m1 == -INFINITY) ? 0.0f : m1;

        // ---- p = exp(s - m) in fp16, P·V (2-pass fp16, V hi/lo via trans) ----
        #pragma unroll
        for (int s = 0; s < 4; s++) {
            uint32_t pa[4];
            #pragma unroll
            for (int h2 = 0; h2 < 2; h2++) {
                const int j = 2 * s + h2;
                float p0 = __expf(Sacc[j][0] - mm0);   // masked: exp(-inf)=0
                float p1 = __expf(Sacc[j][1] - mm0);
                float p2 = __expf(Sacc[j][2] - mm1);
                float p3 = __expf(Sacc[j][3] - mm1);
                __half h0 = __float2half_rn(p0);
                __half h1 = __float2half_rn(p1);
                __half h2b = __float2half_rn(p2);
                __half h3 = __float2half_rn(p3);
                rowsum0 += __half2float(h0) + __half2float(h1);
                rowsum1 += __half2float(h2b) + __half2float(h3);
                pa[h2 * 2 + 0] = pack_h2(h0, h1);
                pa[h2 * 2 + 1] = pack_h2(h2b, h3);
            }
            // V fragments: rows = keys (s*16 + k), cols = d; trans-load
            const uint32_t vrow = (s * 16 + (lane & 7) + 8 * ((lane >> 3) & 1));
            #pragma unroll
            for (int dj = 0; dj < 8; dj += 2) {
                uint32_t vd = stg + A_VOFF + vrow * A_KSTRIDE + (dj * 8 + 8 * (lane >> 4)) * 2;
                uint32_t vh0, vh1, vh2, vh3, vl0, vl1, vl2, vl3;
                LDSM_X4_T(vh0, vh1, vh2, vh3, vd);
                LDSM_X4_T(vl0, vl1, vl2, vl3, vd + A_KMAT);
                mma_f16(Oacc[dj], pa[0], pa[1], pa[2], pa[3], vh0, vh1);
                mma_f16(Oacc[dj], pa[0], pa[1], pa[2], pa[3], vl0, vl1);
                mma_f16(Oacc[dj + 1], pa[0], pa[1], pa[2], pa[3], vh2, vh3);
                mma_f16(Oacc[dj + 1], pa[0], pa[1], pa[2], pa[3], vl2, vl3);
            }
        }
        st++; if (st >= 3) st -= 3;
    }

    // row-sum reduce across the 4 threads sharing a row
    rowsum0 += __shfl_xor_sync(0xFFFFFFFFu, rowsum0, 1);
    rowsum0 += __shfl_xor_sync(0xFFFFFFFFu, rowsum0, 2);
    rowsum1 += __shfl_xor_sync(0xFFFFFFFFu, rowsum1, 1);
    rowsum1 += __shfl_xor_sync(0xFFFFFFFFu, rowsum1, 2);
    const float inv0 = (rowsum0 > 0.0f) ? (1.0f / rowsum0) : 0.0f;
    const float inv1 = (rowsum1 > 0.0f) ? (1.0f / rowsum1) : 0.0f;

    const int b = bh >> 4, h = bh & 15;
    #pragma unroll
    for (int dj = 0; dj < 8; dj++) {
        int d = h * DK + dj * 8 + dc;
        {
            float v0 = Oacc[dj][0] * inv0, v1 = Oacc[dj][1] * inv0;
            size_t idx = ((size_t)(b * LL + row0)) * DMODEL + d;
            store_h2(&Cf[idx], __float2half_rn(v0), __float2half_rn(v1));
        }
        {
            float v0 = Oacc[dj][2] * inv1, v1 = Oacc[dj][3] * inv1;
            size_t idx = ((size_t)(b * LL + row0 + 8)) * DMODEL + d;
            store_h2(&Cf[idx], __float2half_rn(v0), __float2half_rn(v1));
        }
    }
}

// ---------------------------------------------------------------------------
// Launch
// ---------------------------------------------------------------------------
extern "C" void kernel_launch(void* const* d_in, const int* in_sizes, int n_in,
                              void* d_out, int out_size) {
    (void)in_sizes; (void)n_in; (void)out_size;
    const float* query = (const float*)d_in[0];
    const float* key   = (const float*)d_in[1];
    const float* value = (const float*)d_in[2];
    const void*  mask  = d_in[3];
    const float* W_q = (const float*)d_in[4];
    const float* b_q = (const float*)d_in[5];
    const float* W_k = (const float*)d_in[6];
    const float* b_k = (const float*)d_in[7];
    const float* W_v = (const float*)d_in[8];
    const float* b_v = (const float*)d_in[9];
    const float* W_o = (const float*)d_in[10];
    const float* b_o = (const float*)d_in[11];

    __half *in_q, *in_k, *in_v;
    __half *w_qh, *w_ql, *w_kh, *w_kl, *w_vh, *w_vl, *w_oh, *w_ol;
    __half *Vfh, *Vfl, *Cfp;
    __nv_bfloat16 *Qh, *Qlp, *Kh, *Klp;
    cudaGetSymbolAddress((void**)&in_q, g_in_q);
    cudaGetSymbolAddress((void**)&in_k, g_in_k);
    cudaGetSymbolAddress((void**)&in_v, g_in_v);
    cudaGetSymbolAddress((void**)&w_qh, g_w_qh);   cudaGetSymbolAddress((void**)&w_ql, g_w_ql);
    cudaGetSymbolAddress((void**)&w_kh, g_w_kh);   cudaGetSymbolAddress((void**)&w_kl, g_w_kl);
    cudaGetSymbolAddress((void**)&w_vh, g_w_vh);   cudaGetSymbolAddress((void**)&w_vl, g_w_vl);
    cudaGetSymbolAddress((void**)&w_oh, g_w_oh);   cudaGetSymbolAddress((void**)&w_ol, g_w_ol);
    cudaGetSymbolAddress((void**)&Qh, g_Qh);   cudaGetSymbolAddress((void**)&Qlp, g_Ql);
    cudaGetSymbolAddress((void**)&Kh, g_Kh);   cudaGetSymbolAddress((void**)&Klp, g_Kl);
    cudaGetSymbolAddress((void**)&Vfh, g_Vfh); cudaGetSymbolAddress((void**)&Vfl, g_Vfl);
    cudaGetSymbolAddress((void**)&Cfp, g_Cf);

    cudaFuncSetAttribute(mma_gemm, cudaFuncAttributeMaxDynamicSharedMemorySize, GEMM_SMEM);
    cudaFuncSetAttribute(attn_mma, cudaFuncAttributeMaxDynamicSharedMemorySize, ATTN_SMEM);

    convert_mask_bits<<<(MASK_WORDS + 255) / 256, 256>>>(mask);

    const int n4 = MROWS * DMODEL / 4;
    dim3 sg((n4 + 255) / 256, 3);
    conv3_kernel<<<sg, 256>>>((const float4*)query, (const float4*)key, (const float4*)value,
                              (__half2*)in_q, (__half2*)in_k, (__half2*)in_v, n4);

    dim3 tg(DMODEL / 32, DMODEL / 32, 4), tb(32, 32);
    transpose_split4_kernel<<<tg, tb>>>(W_q, W_k, W_v, W_o,
                                        w_qh, w_ql, w_kh, w_kl, w_vh, w_vl, w_oh, w_ol);

    // Fused Q/K/V projections: grid.z = 3 (V output in fp16 hi/lo, mode 2)
    GArgs gp = {};
    gp.A[0] = in_q; gp.Bh[0] = w_qh; gp.Bl[0] = w_ql;
    gp.bias[0] = b_q; gp.oh[0] = Qh;  gp.ol[0] = Qlp; gp.mode[0] = 1;
    gp.A[1] = in_k; gp.Bh[1] = w_kh; gp.Bl[1] = w_kl;
    gp.bias[1] = b_k; gp.oh[1] = Kh;  gp.ol[1] = Klp; gp.mode[1] = 1;
    gp.A[2] = in_v; gp.Bh[2] = w_vh; gp.Bl[2] = w_vl;
    gp.bias[2] = b_v; gp.ohf[2] = Vfh; gp.olf[2] = Vfl; gp.mode[2] = 2;
    dim3 gg3(DMODEL / 128, MROWS / 128, 3);   // (8, 32, 3)
    mma_gemm<<<gg3, 256, GEMM_SMEM>>>(gp);

    dim3 ag(LL / 128, BB * NH);               // (16, 32)
    attn_mma<<<ag, 256, ATTN_SMEM>>>(Qh, Qlp, Kh, Klp, Vfh, Vfl, Cfp);

    // Output projection (A = attention output in single fp16)
    GArgs go = {};
    go.A[0] = Cfp; go.Bh[0] = w_oh; go.Bl[0] = w_ol;
    go.bias[0] = b_o; go.outF[0] = (float*)d_out; go.mode[0] = 0;
    dim3 gg1(DMODEL / 128, MROWS / 128, 1);   // (8, 32, 1)
    mma_gemm<<<gg1, 256, GEMM_SMEM>>>(go);
}

// round 13
// speedup vs baseline: 1.0473x; 1.0473x over previous
#include <cuda_runtime.h>
#include <cuda_bf16.h>
#include <cuda_fp16.h>
#include <math.h>
#include <stdint.h>

// Problem constants
#define BB 2
#define LL 2048
#define DMODEL 1024
#define NH 16
#define DK 64
#define MROWS (BB * LL)          // 4096
#define MASK_W (LL / 32)         // 64 words per row
#define MASK_WORDS (LL * MASK_W)

// ---------------------------------------------------------------------------
// Device scratch (no allocations allowed)
// ---------------------------------------------------------------------------
__device__ __half g_in_q[MROWS * DMODEL], g_in_k[MROWS * DMODEL], g_in_v[MROWS * DMODEL];
__device__ __half g_w_qh[DMODEL * DMODEL], g_w_ql[DMODEL * DMODEL];
__device__ __half g_w_kh[DMODEL * DMODEL], g_w_kl[DMODEL * DMODEL];
__device__ __half g_w_vh[DMODEL * DMODEL], g_w_vl[DMODEL * DMODEL];
__device__ __half g_w_oh[DMODEL * DMODEL], g_w_ol[DMODEL * DMODEL];
__device__ __nv_bfloat16 g_Qh[MROWS * DMODEL], g_Ql[MROWS * DMODEL];   // [b,h,l,d] bf16
__device__ __nv_bfloat16 g_Kh[MROWS * DMODEL], g_Kl[MROWS * DMODEL];   // [b,h,l,d] bf16
__device__ __half g_Vfh[MROWS * DMODEL], g_Vfl[MROWS * DMODEL];        // [b,h,l,d] fp16 hi/lo
__device__ __half g_Cf[MROWS * DMODEL];                                // [b,l,dmodel] fp16
__device__ unsigned int g_maskbits[MASK_WORDS];

// ---------------------------------------------------------------------------
// PTX helpers (portable PTX only: mma.sync / ldmatrix / cp.async)
// ---------------------------------------------------------------------------
__device__ __forceinline__ uint32_t smem_u32(const void* p) {
    uint32_t a;
    asm("{ .reg .u64 t; cvta.to.shared.u64 t, %1; cvt.u32.u64 %0, t; }" : "=r"(a) : "l"(p));
    return a;
}

#define CP_ASYNC16(dst, src) \
    asm volatile("cp.async.cg.shared.global [%0], [%1], 16;" :: "r"(dst), "l"(src))
#define CP_COMMIT() asm volatile("cp.async.commit_group;" ::: "memory")
#define CP_WAIT0()  asm volatile("cp.async.wait_group 0;" ::: "memory")

#define LDSM_X4(r0, r1, r2, r3, addr) \
    asm volatile("ldmatrix.sync.aligned.m8n8.x4.shared.b16 {%0,%1,%2,%3}, [%4];" \
        : "=r"(r0), "=r"(r1), "=r"(r2), "=r"(r3) : "r"(addr))
#define LDSM_X4_T(r0, r1, r2, r3, addr) \
    asm volatile("ldmatrix.sync.aligned.m8n8.x4.trans.shared.b16 {%0,%1,%2,%3}, [%4];" \
        : "=r"(r0), "=r"(r1), "=r"(r2), "=r"(r3) : "r"(addr))

__device__ __forceinline__ void mma_bf16(float* c, uint32_t a0, uint32_t a1, uint32_t a2, uint32_t a3,
                                         uint32_t b0, uint32_t b1) {
    asm volatile("mma.sync.aligned.m16n8k16.row.col.f32.bf16.bf16.f32 "
        "{%0,%1,%2,%3}, {%4,%5,%6,%7}, {%8,%9}, {%0,%1,%2,%3};"
        : "+f"(c[0]), "+f"(c[1]), "+f"(c[2]), "+f"(c[3])
        : "r"(a0), "r"(a1), "r"(a2), "r"(a3), "r"(b0), "r"(b1));
}
__device__ __forceinline__ void mma_f16(float* c, uint32_t a0, uint32_t a1, uint32_t a2, uint32_t a3,
                                        uint32_t b0, uint32_t b1) {
    asm volatile("mma.sync.aligned.m16n8k16.row.col.f32.f16.f16.f32 "
        "{%0,%1,%2,%3}, {%4,%5,%6,%7}, {%8,%9}, {%0,%1,%2,%3};"
        : "+f"(c[0]), "+f"(c[1]), "+f"(c[2]), "+f"(c[3])
        : "r"(a0), "r"(a1), "r"(a2), "r"(a3), "r"(b0), "r"(b1));
}

__device__ __forceinline__ void split2(float x, __nv_bfloat16& h, __nv_bfloat16& l) {
    h = __float2bfloat16(x);
    l = __float2bfloat16(x - __bfloat162float(h));
}
__device__ __forceinline__ void split2h(float x, __half& h, __half& l) {
    h = __float2half_rn(x);
    l = __float2half_rn(x - __half2float(h));
}
__device__ __forceinline__ uint32_t pack_h2(__half e0, __half e1) {
    __half2 t; t.x = e0; t.y = e1;
    return *(uint32_t*)&t;
}
__device__ __forceinline__ void store_bf2(__nv_bfloat16* p, __nv_bfloat16 e0, __nv_bfloat16 e1) {
    __nv_bfloat162 t; t.x = e0; t.y = e1;
    *(__nv_bfloat162*)p = t;
}
__device__ __forceinline__ void store_h2(__half* p, __half e0, __half e1) {
    __half2 t; t.x = e0; t.y = e1;
    *(__half2*)p = t;
}

// ---------------------------------------------------------------------------
// Fused prep kernel: blockIdx.x ranges select mask / conv3 / transpose work.
//   [0, 512):          mask -> bitmask
//   [512, 12800):      q/k/v fp32 -> fp16 (4096 CTAs each)
//   [12800, 16896):    weight transpose+split fp16 hi/lo (1024 CTAs each)
// ---------------------------------------------------------------------------
#define PREP_MASK_CTAS 512
#define PREP_CONV_CTAS 4096
#define PREP_TR_CTAS   1024
#define PREP_TOTAL (PREP_MASK_CTAS + 3 * PREP_CONV_CTAS + 4 * PREP_TR_CTAS)

struct PrepArgs {
    const void* mask;
    const float4 *q, *k, *v;
    __half2 *oq, *ok, *ov;
    const float *wq, *wk, *wv, *wo;
    __half *wqh, *wql, *wkh, *wkl, *wvh, *wvl, *woh, *wol;
};

__global__ __launch_bounds__(256) void prep_kernel(PrepArgs pa) {
    const int cta = blockIdx.x, tid = threadIdx.x;
    if (cta < PREP_MASK_CTAS) {
        // ---- mask -> bits (dtype sniffing: u8 / i32 / f32) ----
        const unsigned int* w = (const unsigned int*)pa.mask;
        bool all_i32 = true, all_f32 = true;
        #pragma unroll
        for (int i = 0; i < 64; i++) {
            unsigned int v = w[i];
            if (v > 1u) all_i32 = false;
            if (v != 0u && v != 0x3F800000u) all_f32 = false;
        }
        int idx = cta * 256 + tid;
        size_t base = (size_t)idx * 32;
        uint32_t bits = 0;
        if (all_i32 || all_f32) {
            const uint4* p = (const uint4*)((const unsigned int*)pa.mask + base);
            #pragma unroll
            for (int g = 0; g < 8; g++) {
                uint4 v = p[g];
                bits |= (v.x != 0u ? 1u : 0u) << (g * 4 + 0);
                bits |= (v.y != 0u ? 1u : 0u) << (g * 4 + 1);
                bits |= (v.z != 0u ? 1u : 0u) << (g * 4 + 2);
                bits |= (v.w != 0u ? 1u : 0u) << (g * 4 + 3);
            }
        } else {
            const uchar4* p = (const uchar4*)((const unsigned char*)pa.mask + base);
            #pragma unroll
            for (int g = 0; g < 8; g++) {
                uchar4 v = p[g];
                bits |= (v.x ? 1u : 0u) << (g * 4 + 0);
                bits |= (v.y ? 1u : 0u) << (g * 4 + 1);
                bits |= (v.z ? 1u : 0u) << (g * 4 + 2);
                bits |= (v.w ? 1u : 0u) << (g * 4 + 3);
            }
        }
        g_maskbits[idx] = bits;
    } else if (cta < PREP_MASK_CTAS + 3 * PREP_CONV_CTAS) {
        // ---- q/k/v fp32 -> single fp16 ----
        int rel = cta - PREP_MASK_CTAS;
        int which = rel / PREP_CONV_CTAS, blk = rel % PREP_CONV_CTAS;
        const float4* in = (which == 0) ? pa.q : (which == 1) ? pa.k : pa.v;
        __half2* out = (which == 0) ? pa.oq : (which == 1) ? pa.ok : pa.ov;
        int i = blk * 256 + tid;
        float4 vv = in[i];
        __half2 a, b;
        a.x = __float2half_rn(vv.x); a.y = __float2half_rn(vv.y);
        b.x = __float2half_rn(vv.z); b.y = __float2half_rn(vv.w);
        out[i * 2] = a;
        out[i * 2 + 1] = b;
    } else {
        // ---- weight transpose + fp16 hi/lo split; one 32x32 tile per CTA ----
        int rel = cta - PREP_MASK_CTAS - 3 * PREP_CONV_CTAS;
        int which = rel / PREP_TR_CTAS, tile = rel % PREP_TR_CTAS;
        const float* in = (which == 0) ? pa.wq : (which == 1) ? pa.wk : (which == 2) ? pa.wv : pa.wo;
        __half* hi = (which == 0) ? pa.wqh : (which == 1) ? pa.wkh : (which == 2) ? pa.wvh : pa.woh;
        __half* lo = (which == 0) ? pa.wql : (which == 1) ? pa.wkl : (which == 2) ? pa.wvl : pa.wol;
        __shared__ float t[32][33];
        int n0 = (tile & 31) * 32, k0 = (tile >> 5) * 32;
        int c = tid & 31, r0 = tid >> 5;          // 8 rows per pass, 4 passes
        #pragma unroll
        for (int p = 0; p < 4; p++) {
            int r = r0 + p * 8;
            t[r][c] = in[(size_t)(k0 + r) * DMODEL + n0 + c];
        }
        __syncthreads();
        #pragma unroll
        for (int p = 0; p < 4; p++) {
            int r = r0 + p * 8;                   // output row within n-block
            float v = t[c][r];                    // transposed read
            int n = n0 + r, k = k0 + c;
            __half h, l;
            split2h(v, h, l);
            hi[(size_t)n * DMODEL + k] = h;
            lo[(size_t)n * DMODEL + k] = l;
        }
    }
}

// ---------------------------------------------------------------------------
// GEMM (fp16, 2-pass): C[m][n] = sum_k A[m,k]*(Wh+Wl)[n,k] + bias[n]
// A single fp16; W fp16 hi/lo. 2-stage cp.async. Warp grid 2x4 (warp tile
// 64x32): cuts per-CTA ldmatrix traffic 80->64 KB/iter.
// mode 0: fp32 out; 1: bf16 hi/lo [b,h,l,d]; 2: fp16 hi/lo [b,h,l,d].
// ---------------------------------------------------------------------------
#define G_STRIDE 80
#define G_MAT    10240          // 128*80
#define G_STAGE  30720          // 3 mats
#define GEMM_SMEM (2 * G_STAGE) // 61440

struct GArgs {
    const __half *A[3], *Bh[3], *Bl[3];
    const float* bias[3];
    float* outF[3];
    __nv_bfloat16 *oh[3], *ol[3];
    __half *ohf[3], *olf[3];
    int mode[3];
};

__global__ __launch_bounds__(256, 2) void mma_gemm(GArgs ga)
{
    extern __shared__ char smem[];
    const uint32_t sb = smem_u32(smem);
    const int z = blockIdx.z;
    const __half* __restrict__ A  = ga.A[z];
    const __half* __restrict__ Bh = ga.Bh[z];
    const __half* __restrict__ Bl = ga.Bl[z];
    const float* __restrict__ bias = ga.bias[z];
    const int mode = ga.mode[z];

    const int tid = threadIdx.x, wid = tid >> 5, lane = tid & 31;
    const int bm = blockIdx.y * 128, bn = blockIdx.x * 128;
    const int warpM = (wid >> 2) * 64, warpN = (wid & 3) * 32;

    float acc[4][4][4];   // [mi][nj][4]
    #pragma unroll
    for (int i = 0; i < 4; i++)
        #pragma unroll
        for (int j = 0; j < 4; j++)
            #pragma unroll
            for (int r = 0; r < 4; r++) acc[i][j][r] = 0.0f;

    const __half* srcs[3] = {A, Bh, Bl};

    // prologue: tile 0 -> stage 0   (3 mats x 128 rows x 4 segs = 1536 chunks)
    #pragma unroll
    for (int i = 0; i < 6; i++) {
        int c = tid + i * 256;
        int mat = c >> 9, r = (c >> 2) & 127, seg = c & 3;
        uint32_t dst = sb + mat * G_MAT + r * G_STRIDE + seg * 16;
        int row = (mat < 1) ? (bm + r) : (bn + r);
        CP_ASYNC16(dst, srcs[mat] + (size_t)row * DMODEL + seg * 8);
    }
    CP_COMMIT();

    for (int it = 0; it < 32; it++) {
        CP_WAIT0();
        __syncthreads();
        if (it + 1 < 32) {
            const int k0 = (it + 1) * 32;
            const uint32_t stg = sb + ((it + 1) & 1) * G_STAGE;
            #pragma unroll
            for (int i = 0; i < 6; i++) {
                int c = tid + i * 256;
                int mat = c >> 9, r = (c >> 2) & 127, seg = c & 3;
                uint32_t dst = stg + mat * G_MAT + r * G_STRIDE + seg * 16;
                int row = (mat < 1) ? (bm + r) : (bn + r);
                CP_ASYNC16(dst, srcs[mat] + (size_t)row * DMODEL + k0 + seg * 8);
            }
            CP_COMMIT();
        }

        const uint32_t stg = sb + (it & 1) * G_STAGE;
        const uint32_t aRow = warpM + (lane & 15);
        #pragma unroll
        for (int ks = 0; ks < 2; ks++) {
            const uint32_t kOffA = (ks * 16 + 8 * (lane >> 4)) * 2;
            const uint32_t kOffB = (ks * 16 + 8 * ((lane >> 3) & 1)) * 2;
            uint32_t ah[4][4];
            #pragma unroll
            for (int mi = 0; mi < 4; mi++) {
                uint32_t ad = stg + (aRow + mi * 16) * G_STRIDE + kOffA;
                LDSM_X4(ah[mi][0], ah[mi][1], ah[mi][2], ah[mi][3], ad);
            }
            #pragma unroll
            for (int nj = 0; nj < 4; nj += 2) {
                uint32_t bd = stg + G_MAT
                            + (warpN + (nj + (lane >> 4)) * 8 + (lane & 7)) * G_STRIDE + kOffB;
                uint32_t bh0, bh1, bh2, bh3, bl0, bl1, bl2, bl3;
                LDSM_X4(bh0, bh1, bh2, bh3, bd);
                LDSM_X4(bl0, bl1, bl2, bl3, bd + G_MAT);
                #pragma unroll
                for (int mi = 0; mi < 4; mi++) {
                    mma_f16(acc[mi][nj], ah[mi][0], ah[mi][1], ah[mi][2], ah[mi][3], bh0, bh1);
                    mma_f16(acc[mi][nj], ah[mi][0], ah[mi][1], ah[mi][2], ah[mi][3], bl0, bl1);
                    mma_f16(acc[mi][nj + 1], ah[mi][0], ah[mi][1], ah[mi][2], ah[mi][3], bh2, bh3);
                    mma_f16(acc[mi][nj + 1], ah[mi][0], ah[mi][1], ah[mi][2], ah[mi][3], bl2, bl3);
                }
            }
        }
    }

    // epilogue
    #pragma unroll
    for (int mi = 0; mi < 4; mi++) {
        #pragma unroll
        for (int nj = 0; nj < 4; nj++) {
            int n = bn + warpN + nj * 8 + 2 * (lane & 3);
            float bias0 = bias[n], bias1 = bias[n + 1];
            #pragma unroll
            for (int half = 0; half < 2; half++) {
                int m = bm + warpM + mi * 16 + (lane >> 2) + half * 8;
                float v0 = acc[mi][nj][half * 2 + 0] + bias0;
                float v1 = acc[mi][nj][half * 2 + 1] + bias1;
                if (mode == 0) {
                    float2 o; o.x = v0; o.y = v1;
                    *(float2*)&ga.outF[z][(size_t)m * DMODEL + n] = o;
                } else {
                    int b = m >> 11, l = m & 2047;
                    int h = n >> 6, d = n & 63;
                    size_t idx = (((size_t)(b * NH + h)) * LL + l) * DK + d;
                    if (mode == 1) {
                        __nv_bfloat16 h0, h1, l0, l1;
                        split2(v0, h0, l0); split2(v1, h1, l1);
                        store_bf2(&ga.oh[z][idx], h0, h1);
                        store_bf2(&ga.ol[z][idx], l0, l1);
                    } else {
                        __half h0, h1, l0, l1;
                        split2h(v0, h0, l0); split2h(v1, h1, l1);
                        store_h2(&ga.ohf[z][idx], h0, h1);
                        store_h2(&ga.olf[z][idx], l0, l1);
                    }
                }
            }
        }
    }
}

// ---------------------------------------------------------------------------
// Flash attention, ONLINE softmax, 2-stage cp.async.
// CTA: 128 queries x one (b,h); 32 key tiles of 64; 8 warps, warp = 16 queries.
// S = bf16 3-pass. P = single fp16 (p = exp(s - m) <= 1).
// P·V = fp16 2-pass (V hi/lo fp16) via mma_f16 + ldmatrix.trans.
// ---------------------------------------------------------------------------
#define A_KSTRIDE 144           // 64 elems * 2B + 16 pad
#define A_KMAT    9216          // 64*144
#define A_VOFF    18432         // 2*A_KMAT (V hi/lo follow K hi/lo)
#define A_STAGE   36864         // 4 mats * 9216
#define ATTN_SMEM (2 * A_STAGE) // 73728

__global__ __launch_bounds__(256, 2) void attn_mma(
    const __nv_bfloat16* __restrict__ Qh, const __nv_bfloat16* __restrict__ Ql,
    const __nv_bfloat16* __restrict__ Kh, const __nv_bfloat16* __restrict__ Kl,
    const __half* __restrict__ Vh, const __half* __restrict__ Vl,
    __half* __restrict__ Cf)
{
    extern __shared__ char smem[];
    const uint32_t sb = smem_u32(smem);
    const int tid = threadIdx.x, wid = tid >> 5, lane = tid & 31;
    const int bh = blockIdx.y, q0 = blockIdx.x * 128;
    const int warpM = wid * 16;

    const __nv_bfloat16* qbh = Qh + (size_t)bh * LL * DK;
    const __nv_bfloat16* qbl = Ql + (size_t)bh * LL * DK;
    const __nv_bfloat16* srcs[4] = {
        Kh + (size_t)bh * LL * DK, Kl + (size_t)bh * LL * DK,
        (const __nv_bfloat16*)(Vh + (size_t)bh * LL * DK),
        (const __nv_bfloat16*)(Vl + (size_t)bh * LL * DK)};

    // ---- Q preload into smem, extract fragments, reuse ----
    #pragma unroll
    for (int i = 0; i < 8; i++) {
        int c = tid + i * 256;                 // 2048 chunks: 2 mats x 128 rows x 8 segs
        int mat = c >> 10, r = (c >> 3) & 127, seg = c & 7;
        const __nv_bfloat16* src = (mat ? qbl : qbh) + (size_t)(q0 + r) * DK + seg * 8;
        *(uint4*)(smem + mat * 18432 + r * A_KSTRIDE + seg * 16) = *(const uint4*)src;
    }
    __syncthreads();
    uint32_t qh[4][4], ql[4][4];
    {
        const uint32_t aRow = warpM + (lane & 15);
        #pragma unroll
        for (int ks = 0; ks < 4; ks++) {
            uint32_t ad = sb + aRow * A_KSTRIDE + (ks * 16 + 8 * (lane >> 4)) * 2;
            LDSM_X4(qh[ks][0], qh[ks][1], qh[ks][2], qh[ks][3], ad);
            LDSM_X4(ql[ks][0], ql[ks][1], ql[ks][2], ql[ks][3], ad + 18432);
        }
    }
    __syncthreads();

    // ---- K/V prologue: tile 0 -> stage 0 ----
    #pragma unroll
    for (int i = 0; i < 8; i++) {
        int c = tid + i * 256;
        int mat = c >> 9, r = (c >> 3) & 63, seg = c & 7;
        uint32_t dst = sb + mat * A_KMAT + r * A_KSTRIDE + seg * 16;
        CP_ASYNC16(dst, srcs[mat] + (size_t)r * DK + seg * 8);
    }
    CP_COMMIT();

    float Oacc[8][4];
    #pragma unroll
    for (int j = 0; j < 8; j++)
        #pragma unroll
        for (int r = 0; r < 4; r++) Oacc[j][r] = 0.0f;
    float rowsum0 = 0.0f, rowsum1 = 0.0f;
    float m0 = -INFINITY, m1 = -INFINITY;

    const int row0 = q0 + warpM + (lane >> 2);
    const int dc = 2 * (lane & 3);

    for (int kt = 0; kt < 32; kt++) {
        // mask bits (gmem; overlap with wait)
        uint32_t mw0[2], mw1[2];
        #pragma unroll
        for (int w = 0; w < 2; w++) {
            mw0[w] = g_maskbits[(size_t)row0 * MASK_W + kt * 2 + w];
            mw1[w] = g_maskbits[(size_t)(row0 + 8) * MASK_W + kt * 2 + w];
        }

        CP_WAIT0();
        __syncthreads();
        if (kt + 1 < 32) {
            const int kbase = (kt + 1) * 64;
            const uint32_t stg = sb + ((kt + 1) & 1) * A_STAGE;
            #pragma unroll
            for (int i = 0; i < 8; i++) {
                int c = tid + i * 256;
                int mat = c >> 9, r = (c >> 3) & 63, seg = c & 7;
                uint32_t dst = stg + mat * A_KMAT + r * A_KSTRIDE + seg * 16;
                CP_ASYNC16(dst, srcs[mat] + (size_t)(kbase + r) * DK + seg * 8);
            }
            CP_COMMIT();
        }

        const uint32_t stg = sb + (kt & 1) * A_STAGE;

        // ---- S = Q K^T (bf16 3-pass) ----
        float Sacc[8][4];
        #pragma unroll
        for (int j = 0; j < 8; j++)
            #pragma unroll
            for (int r = 0; r < 4; r++) Sacc[j][r] = 0.0f;

        #pragma unroll
        for (int ks = 0; ks < 4; ks++) {
            const uint32_t kOffB = (ks * 16 + 8 * ((lane >> 3) & 1)) * 2;
            #pragma unroll
            for (int j = 0; j < 8; j += 2) {
                uint32_t bd = stg + ((j + (lane >> 4)) * 8 + (lane & 7)) * A_KSTRIDE + kOffB;
                uint32_t bh0, bh1, bh2, bh3, bl0, bl1, bl2, bl3;
                LDSM_X4(bh0, bh1, bh2, bh3, bd);
                LDSM_X4(bl0, bl1, bl2, bl3, bd + A_KMAT);
                mma_bf16(Sacc[j], qh[ks][0], qh[ks][1], qh[ks][2], qh[ks][3], bh0, bh1);
                mma_bf16(Sacc[j], qh[ks][0], qh[ks][1], qh[ks][2], qh[ks][3], bl0, bl1);
                mma_bf16(Sacc[j], ql[ks][0], ql[ks][1], ql[ks][2], ql[ks][3], bh0, bh1);
                mma_bf16(Sacc[j + 1], qh[ks][0], qh[ks][1], qh[ks][2], qh[ks][3], bh2, bh3);
                mma_bf16(Sacc[j + 1], qh[ks][0], qh[ks][1], qh[ks][2], qh[ks][3], bl2, bl3);
                mma_bf16(Sacc[j + 1], ql[ks][0], ql[ks][1], ql[ks][2], ql[ks][3], bh2, bh3);
            }
        }

        // ---- apply mask (s -> -inf) + tile row max ----
        float tmax0 = -INFINITY, tmax1 = -INFINITY;
        #pragma unroll
        for (int j = 0; j < 8; j++) {
            const int sh = (j & 3) * 8 + dc;
            uint32_t b0 = (mw0[j >> 2] >> sh) & 3u;
            uint32_t b1 = (mw1[j >> 2] >> sh) & 3u;
            if (b0 & 1u) Sacc[j][0] = -INFINITY;
            if (b0 & 2u) Sacc[j][1] = -INFINITY;
            if (b1 & 1u) Sacc[j][2] = -INFINITY;
            if (b1 & 2u) Sacc[j][3] = -INFINITY;
            tmax0 = fmaxf(tmax0, fmaxf(Sacc[j][0], Sacc[j][1]));
            tmax1 = fmaxf(tmax1, fmaxf(Sacc[j][2], Sacc[j][3]));
        }
        tmax0 = fmaxf(tmax0, __shfl_xor_sync(0xFFFFFFFFu, tmax0, 1));
        tmax0 = fmaxf(tmax0, __shfl_xor_sync(0xFFFFFFFFu, tmax0, 2));
        tmax1 = fmaxf(tmax1, __shfl_xor_sync(0xFFFFFFFFu, tmax1, 1));
        tmax1 = fmaxf(tmax1, __shfl_xor_sync(0xFFFFFFFFu, tmax1, 2));
        if (tmax0 > m0) {
            float sc = __expf(m0 - tmax0);   // m0=-inf -> 0; Oacc/rowsum were 0
            rowsum0 *= sc;
            #pragma unroll
            for (int dj = 0; dj < 8; dj++) { Oacc[dj][0] *= sc; Oacc[dj][1] *= sc; }
            m0 = tmax0;
        }
        if (tmax1 > m1) {
            float sc = __expf(m1 - tmax1);
            rowsum1 *= sc;
            #pragma unroll
            for (int dj = 0; dj < 8; dj++) { Oacc[dj][2] *= sc; Oacc[dj][3] *= sc; }
            m1 = tmax1;
        }
        const float mm0 = (m0 == -INFINITY) ? 0.0f : m0;
        const float mm1 = (m1 == -INFINITY) ? 0.0f : m1;

        // ---- p = exp(s - m) in fp16, P·V (2-pass fp16, V hi/lo via trans) ----
        #pragma unroll
        for (int s = 0; s < 4; s++) {
            uint32_t pa[4];
            #pragma unroll
            for (int h2 = 0; h2 < 2; h2++) {
                const int j = 2 * s + h2;
                float p0 = __expf(Sacc[j][0] - mm0);   // masked: exp(-inf)=0
                float p1 = __expf(Sacc[j][1] - mm0);
                float p2 = __expf(Sacc[j][2] - mm1);
                float p3 = __expf(Sacc[j][3] - mm1);
                __half h0 = __float2half_rn(p0);
                __half h1 = __float2half_rn(p1);
                __half h2b = __float2half_rn(p2);
                __half h3 = __float2half_rn(p3);
                rowsum0 += __half2float(h0) + __half2float(h1);
                rowsum1 += __half2float(h2b) + __half2float(h3);
                pa[h2 * 2 + 0] = pack_h2(h0, h1);
                pa[h2 * 2 + 1] = pack_h2(h2b, h3);
            }
            // V fragments: rows = keys (s*16 + k), cols = d; trans-load
            const uint32_t vrow = (s * 16 + (lane & 7) + 8 * ((lane >> 3) & 1));
            #pragma unroll
            for (int dj = 0; dj < 8; dj += 2) {
                uint32_t vd = stg + A_VOFF + vrow * A_KSTRIDE + (dj * 8 + 8 * (lane >> 4)) * 2;
                uint32_t vh0, vh1, vh2, vh3, vl0, vl1, vl2, vl3;
                LDSM_X4_T(vh0, vh1, vh2, vh3, vd);
                LDSM_X4_T(vl0, vl1, vl2, vl3, vd + A_KMAT);
                mma_f16(Oacc[dj], pa[0], pa[1], pa[2], pa[3], vh0, vh1);
                mma_f16(Oacc[dj], pa[0], pa[1], pa[2], pa[3], vl0, vl1);
                mma_f16(Oacc[dj + 1], pa[0], pa[1], pa[2], pa[3], vh2, vh3);
                mma_f16(Oacc[dj + 1], pa[0], pa[1], pa[2], pa[3], vl2, vl3);
            }
        }
    }

    // row-sum reduce across the 4 threads sharing a row
    rowsum0 += __shfl_xor_sync(0xFFFFFFFFu, rowsum0, 1);
    rowsum0 += __shfl_xor_sync(0xFFFFFFFFu, rowsum0, 2);
    rowsum1 += __shfl_xor_sync(0xFFFFFFFFu, rowsum1, 1);
    rowsum1 += __shfl_xor_sync(0xFFFFFFFFu, rowsum1, 2);
    const float inv0 = (rowsum0 > 0.0f) ? (1.0f / rowsum0) : 0.0f;
    const float inv1 = (rowsum1 > 0.0f) ? (1.0f / rowsum1) : 0.0f;

    const int b = bh >> 4, h = bh & 15;
    #pragma unroll
    for (int dj = 0; dj < 8; dj++) {
        int d = h * DK + dj * 8 + dc;
        {
            float v0 = Oacc[dj][0] * inv0, v1 = Oacc[dj][1] * inv0;
            size_t idx = ((size_t)(b * LL + row0)) * DMODEL + d;
            store_h2(&Cf[idx], __float2half_rn(v0), __float2half_rn(v1));
        }
        {
            float v0 = Oacc[dj][2] * inv1, v1 = Oacc[dj][3] * inv1;
            size_t idx = ((size_t)(b * LL + row0 + 8)) * DMODEL + d;
            store_h2(&Cf[idx], __float2half_rn(v0), __float2half_rn(v1));
        }
    }
}

// ---------------------------------------------------------------------------
// Launch
// ---------------------------------------------------------------------------
extern "C" void kernel_launch(void* const* d_in, const int* in_sizes, int n_in,
                              void* d_out, int out_size) {
    (void)in_sizes; (void)n_in; (void)out_size;
    const float* query = (const float*)d_in[0];
    const float* key   = (const float*)d_in[1];
    const float* value = (const float*)d_in[2];
    const void*  mask  = d_in[3];
    const float* W_q = (const float*)d_in[4];
    const float* b_q = (const float*)d_in[5];
    const float* W_k = (const float*)d_in[6];
    const float* b_k = (const float*)d_in[7];
    const float* W_v = (const float*)d_in[8];
    const float* b_v = (const float*)d_in[9];
    const float* W_o = (const float*)d_in[10];
    const float* b_o = (const float*)d_in[11];

    __half *in_q, *in_k, *in_v;
    __half *w_qh, *w_ql, *w_kh, *w_kl, *w_vh, *w_vl, *w_oh, *w_ol;
    __half *Vfh, *Vfl, *Cfp;
    __nv_bfloat16 *Qh, *Qlp, *Kh, *Klp;
    cudaGetSymbolAddress((void**)&in_q, g_in_q);
    cudaGetSymbolAddress((void**)&in_k, g_in_k);
    cudaGetSymbolAddress((void**)&in_v, g_in_v);
    cudaGetSymbolAddress((void**)&w_qh, g_w_qh);   cudaGetSymbolAddress((void**)&w_ql, g_w_ql);
    cudaGetSymbolAddress((void**)&w_kh, g_w_kh);   cudaGetSymbolAddress((void**)&w_kl, g_w_kl);
    cudaGetSymbolAddress((void**)&w_vh, g_w_vh);   cudaGetSymbolAddress((void**)&w_vl, g_w_vl);
    cudaGetSymbolAddress((void**)&w_oh, g_w_oh);   cudaGetSymbolAddress((void**)&w_ol, g_w_ol);
    cudaGetSymbolAddress((void**)&Qh, g_Qh);   cudaGetSymbolAddress((void**)&Qlp, g_Ql);
    cudaGetSymbolAddress((void**)&Kh, g_Kh);   cudaGetSymbolAddress((void**)&Klp, g_Kl);
    cudaGetSymbolAddress((void**)&Vfh, g_Vfh); cudaGetSymbolAddress((void**)&Vfl, g_Vfl);
    cudaGetSymbolAddress((void**)&Cfp, g_Cf);

    cudaFuncSetAttribute(mma_gemm, cudaFuncAttributeMaxDynamicSharedMemorySize, GEMM_SMEM);
    cudaFuncSetAttribute(attn_mma, cudaFuncAttributeMaxDynamicSharedMemorySize, ATTN_SMEM);

    // Fused prep: mask bits + q/k/v fp16 convert + weight transpose/split
    PrepArgs pa;
    pa.mask = mask;
    pa.q = (const float4*)query; pa.k = (const float4*)key; pa.v = (const float4*)value;
    pa.oq = (__half2*)in_q; pa.ok = (__half2*)in_k; pa.ov = (__half2*)in_v;
    pa.wq = W_q; pa.wk = W_k; pa.wv = W_v; pa.wo = W_o;
    pa.wqh = w_qh; pa.wql = w_ql; pa.wkh = w_kh; pa.wkl = w_kl;
    pa.wvh = w_vh; pa.wvl = w_vl; pa.woh = w_oh; pa.wol = w_ol;
    prep_kernel<<<PREP_TOTAL, 256>>>(pa);

    // Fused Q/K/V projections: grid.z = 3 (V output in fp16 hi/lo, mode 2)
    GArgs gp = {};
    gp.A[0] = in_q; gp.Bh[0] = w_qh; gp.Bl[0] = w_ql;
    gp.bias[0] = b_q; gp.oh[0] = Qh;  gp.ol[0] = Qlp; gp.mode[0] = 1;
    gp.A[1] = in_k; gp.Bh[1] = w_kh; gp.Bl[1] = w_kl;
    gp.bias[1] = b_k; gp.oh[1] = Kh;  gp.ol[1] = Klp; gp.mode[1] = 1;
    gp.A[2] = in_v; gp.Bh[2] = w_vh; gp.Bl[2] = w_vl;
    gp.bias[2] = b_v; gp.ohf[2] = Vfh; gp.olf[2] = Vfl; gp.mode[2] = 2;
    dim3 gg3(DMODEL / 128, MROWS / 128, 3);   // (8, 32, 3)
    mma_gemm<<<gg3, 256, GEMM_SMEM>>>(gp);

    dim3 ag(LL / 128, BB * NH);               // (16, 32)
    attn_mma<<<ag, 256, ATTN_SMEM>>>(Qh, Qlp, Kh, Klp, Vfh, Vfl, Cfp);

    // Output projection (A = attention output in single fp16)
    GArgs go = {};
    go.A[0] = Cfp; go.Bh[0] = w_oh; go.Bl[0] = w_ol;
    go.bias[0] = b_o; go.outF[0] = (float*)d_out; go.mode[0] = 0;
    dim3 gg1(DMODEL / 128, MROWS / 128, 1);   // (8, 32, 1)
    mma_gemm<<<gg1, 256, GEMM_SMEM>>>(go);
}

// round 14
// speedup vs baseline: 1.1834x; 1.1300x over previous
#include <cuda_runtime.h>
#include <cuda_bf16.h>
#include <cuda_fp16.h>
#include <math.h>
#include <stdint.h>

// Problem constants
#define BB 2
#define LL 2048
#define DMODEL 1024
#define NH 16
#define DK 64
#define MROWS (BB * LL)          // 4096
#define MASK_W (LL / 32)         // 64 words per row
#define MASK_WORDS (LL * MASK_W)

// ---------------------------------------------------------------------------
// Device scratch (no allocations allowed)
// ---------------------------------------------------------------------------
__device__ __half g_in_q[MROWS * DMODEL], g_in_k[MROWS * DMODEL], g_in_v[MROWS * DMODEL];
__device__ __half g_w_qh[DMODEL * DMODEL], g_w_ql[DMODEL * DMODEL];
__device__ __half g_w_kh[DMODEL * DMODEL], g_w_kl[DMODEL * DMODEL];
__device__ __half g_w_vh[DMODEL * DMODEL], g_w_vl[DMODEL * DMODEL];
__device__ __half g_w_oh[DMODEL * DMODEL], g_w_ol[DMODEL * DMODEL];
__device__ __nv_bfloat16 g_Qh[MROWS * DMODEL], g_Ql[MROWS * DMODEL];   // [b,h,l,d] bf16
__device__ __nv_bfloat16 g_Kh[MROWS * DMODEL], g_Kl[MROWS * DMODEL];   // [b,h,l,d] bf16
__device__ __half g_Vf[MROWS * DMODEL];                                // [b,h,l,d] fp16 single
__device__ __half g_Cf[MROWS * DMODEL];                                // [b,l,dmodel] fp16
__device__ unsigned int g_maskbits[MASK_WORDS];

// ---------------------------------------------------------------------------
// PTX helpers (portable PTX only: mma.sync / ldmatrix / cp.async)
// ---------------------------------------------------------------------------
__device__ __forceinline__ uint32_t smem_u32(const void* p) {
    uint32_t a;
    asm("{ .reg .u64 t; cvta.to.shared.u64 t, %1; cvt.u32.u64 %0, t; }" : "=r"(a) : "l"(p));
    return a;
}

#define CP_ASYNC16(dst, src) \
    asm volatile("cp.async.cg.shared.global [%0], [%1], 16;" :: "r"(dst), "l"(src))
#define CP_COMMIT() asm volatile("cp.async.commit_group;" ::: "memory")
#define CP_WAIT0()  asm volatile("cp.async.wait_group 0;" ::: "memory")

#define LDSM_X4(r0, r1, r2, r3, addr) \
    asm volatile("ldmatrix.sync.aligned.m8n8.x4.shared.b16 {%0,%1,%2,%3}, [%4];" \
        : "=r"(r0), "=r"(r1), "=r"(r2), "=r"(r3) : "r"(addr))
#define LDSM_X4_T(r0, r1, r2, r3, addr) \
    asm volatile("ldmatrix.sync.aligned.m8n8.x4.trans.shared.b16 {%0,%1,%2,%3}, [%4];" \
        : "=r"(r0), "=r"(r1), "=r"(r2), "=r"(r3) : "r"(addr))

__device__ __forceinline__ void mma_bf16(float* c, uint32_t a0, uint32_t a1, uint32_t a2, uint32_t a3,
                                         uint32_t b0, uint32_t b1) {
    asm volatile("mma.sync.aligned.m16n8k16.row.col.f32.bf16.bf16.f32 "
        "{%0,%1,%2,%3}, {%4,%5,%6,%7}, {%8,%9}, {%0,%1,%2,%3};"
        : "+f"(c[0]), "+f"(c[1]), "+f"(c[2]), "+f"(c[3])
        : "r"(a0), "r"(a1), "r"(a2), "r"(a3), "r"(b0), "r"(b1));
}
__device__ __forceinline__ void mma_f16(float* c, uint32_t a0, uint32_t a1, uint32_t a2, uint32_t a3,
                                        uint32_t b0, uint32_t b1) {
    asm volatile("mma.sync.aligned.m16n8k16.row.col.f32.f16.f16.f32 "
        "{%0,%1,%2,%3}, {%4,%5,%6,%7}, {%8,%9}, {%0,%1,%2,%3};"
        : "+f"(c[0]), "+f"(c[1]), "+f"(c[2]), "+f"(c[3])
        : "r"(a0), "r"(a1), "r"(a2), "r"(a3), "r"(b0), "r"(b1));
}

__device__ __forceinline__ void split2(float x, __nv_bfloat16& h, __nv_bfloat16& l) {
    h = __float2bfloat16(x);
    l = __float2bfloat16(x - __bfloat162float(h));
}
__device__ __forceinline__ void split2h(float x, __half& h, __half& l) {
    h = __float2half_rn(x);
    l = __float2half_rn(x - __half2float(h));
}
__device__ __forceinline__ uint32_t pack_h2(__half e0, __half e1) {
    __half2 t; t.x = e0; t.y = e1;
    return *(uint32_t*)&t;
}
__device__ __forceinline__ void store_bf2(__nv_bfloat16* p, __nv_bfloat16 e0, __nv_bfloat16 e1) {
    __nv_bfloat162 t; t.x = e0; t.y = e1;
    *(__nv_bfloat162*)p = t;
}
__device__ __forceinline__ void store_h2(__half* p, __half e0, __half e1) {
    __half2 t; t.x = e0; t.y = e1;
    *(__half2*)p = t;
}

// ---------------------------------------------------------------------------
// Fused prep kernel: blockIdx.x ranges select mask / conv3 / transpose work.
// ---------------------------------------------------------------------------
#define PREP_MASK_CTAS 512
#define PREP_CONV_CTAS 4096
#define PREP_TR_CTAS   1024
#define PREP_TOTAL (PREP_MASK_CTAS + 3 * PREP_CONV_CTAS + 4 * PREP_TR_CTAS)

struct PrepArgs {
    const void* mask;
    const float4 *q, *k, *v;
    __half2 *oq, *ok, *ov;
    const float *wq, *wk, *wv, *wo;
    __half *wqh, *wql, *wkh, *wkl, *wvh, *wvl, *woh, *wol;
};

__global__ __launch_bounds__(256) void prep_kernel(PrepArgs pa) {
    const int cta = blockIdx.x, tid = threadIdx.x;
    if (cta < PREP_MASK_CTAS) {
        const unsigned int* w = (const unsigned int*)pa.mask;
        bool all_i32 = true, all_f32 = true;
        #pragma unroll
        for (int i = 0; i < 64; i++) {
            unsigned int v = w[i];
            if (v > 1u) all_i32 = false;
            if (v != 0u && v != 0x3F800000u) all_f32 = false;
        }
        int idx = cta * 256 + tid;
        size_t base = (size_t)idx * 32;
        uint32_t bits = 0;
        if (all_i32 || all_f32) {
            const uint4* p = (const uint4*)((const unsigned int*)pa.mask + base);
            #pragma unroll
            for (int g = 0; g < 8; g++) {
                uint4 v = p[g];
                bits |= (v.x != 0u ? 1u : 0u) << (g * 4 + 0);
                bits |= (v.y != 0u ? 1u : 0u) << (g * 4 + 1);
                bits |= (v.z != 0u ? 1u : 0u) << (g * 4 + 2);
                bits |= (v.w != 0u ? 1u : 0u) << (g * 4 + 3);
            }
        } else {
            const uchar4* p = (const uchar4*)((const unsigned char*)pa.mask + base);
            #pragma unroll
            for (int g = 0; g < 8; g++) {
                uchar4 v = p[g];
                bits |= (v.x ? 1u : 0u) << (g * 4 + 0);
                bits |= (v.y ? 1u : 0u) << (g * 4 + 1);
                bits |= (v.z ? 1u : 0u) << (g * 4 + 2);
                bits |= (v.w ? 1u : 0u) << (g * 4 + 3);
            }
        }
        g_maskbits[idx] = bits;
    } else if (cta < PREP_MASK_CTAS + 3 * PREP_CONV_CTAS) {
        int rel = cta - PREP_MASK_CTAS;
        int which = rel / PREP_CONV_CTAS, blk = rel % PREP_CONV_CTAS;
        const float4* in = (which == 0) ? pa.q : (which == 1) ? pa.k : pa.v;
        __half2* out = (which == 0) ? pa.oq : (which == 1) ? pa.ok : pa.ov;
        int i = blk * 256 + tid;
        float4 vv = in[i];
        __half2 a, b;
        a.x = __float2half_rn(vv.x); a.y = __float2half_rn(vv.y);
        b.x = __float2half_rn(vv.z); b.y = __float2half_rn(vv.w);
        out[i * 2] = a;
        out[i * 2 + 1] = b;
    } else {
        int rel = cta - PREP_MASK_CTAS - 3 * PREP_CONV_CTAS;
        int which = rel / PREP_TR_CTAS, tile = rel % PREP_TR_CTAS;
        const float* in = (which == 0) ? pa.wq : (which == 1) ? pa.wk : (which == 2) ? pa.wv : pa.wo;
        __half* hi = (which == 0) ? pa.wqh : (which == 1) ? pa.wkh : (which == 2) ? pa.wvh : pa.woh;
        __half* lo = (which == 0) ? pa.wql : (which == 1) ? pa.wkl : (which == 2) ? pa.wvl : pa.wol;
        __shared__ float t[32][33];
        int n0 = (tile & 31) * 32, k0 = (tile >> 5) * 32;
        int c = tid & 31, r0 = tid >> 5;
        #pragma unroll
        for (int p = 0; p < 4; p++) {
            int r = r0 + p * 8;
            t[r][c] = in[(size_t)(k0 + r) * DMODEL + n0 + c];
        }
        __syncthreads();
        #pragma unroll
        for (int p = 0; p < 4; p++) {
            int r = r0 + p * 8;
            float v = t[c][r];
            int n = n0 + r, k = k0 + c;
            __half h, l;
            split2h(v, h, l);
            hi[(size_t)n * DMODEL + k] = h;
            lo[(size_t)n * DMODEL + k] = l;
        }
    }
}

// ---------------------------------------------------------------------------
// GEMM (fp16): C[m][n] = sum_k A[m,k]*W[n,k] + bias[n]
// np=2: W = Wh + Wl (2-pass). np=1: W = Wh only (1-pass).
// mode 0: fp32 out; 1: bf16 hi/lo [b,h,l,d]; 3: fp16 single [b,h,l,d].
// ---------------------------------------------------------------------------
#define G_STRIDE 80
#define G_MAT    10240          // 128*80
#define G_STAGE  30720          // 3 mats
#define GEMM_SMEM (2 * G_STAGE) // 61440

struct GArgs {
    const __half *A[3], *Bh[3], *Bl[3];
    const float* bias[3];
    float* outF[3];
    __nv_bfloat16 *oh[3], *ol[3];
    __half *ohf[3];
    int mode[3];
    int np[3];
};

__global__ __launch_bounds__(256, 2) void mma_gemm(GArgs ga)
{
    extern __shared__ char smem[];
    const uint32_t sb = smem_u32(smem);
    const int z = blockIdx.z;
    const __half* __restrict__ A  = ga.A[z];
    const __half* __restrict__ Bh = ga.Bh[z];
    const __half* __restrict__ Bl = ga.Bl[z];
    const float* __restrict__ bias = ga.bias[z];
    const int mode = ga.mode[z];
    const int np = ga.np[z];

    const int tid = threadIdx.x, wid = tid >> 5, lane = tid & 31;
    const int bm = blockIdx.y * 128, bn = blockIdx.x * 128;
    const int warpM = (wid >> 2) * 64, warpN = (wid & 3) * 32;

    float acc[4][4][4];
    #pragma unroll
    for (int i = 0; i < 4; i++)
        #pragma unroll
        for (int j = 0; j < 4; j++)
            #pragma unroll
            for (int r = 0; r < 4; r++) acc[i][j][r] = 0.0f;

    const __half* srcs[3] = {A, Bh, Bl};

    // prologue: tile 0 -> stage 0
    #pragma unroll
    for (int i = 0; i < 6; i++) {
        int c = tid + i * 256;
        int mat = c >> 9, r = (c >> 2) & 127, seg = c & 3;
        if (mat != 2 || np == 2) {
            uint32_t dst = sb + mat * G_MAT + r * G_STRIDE + seg * 16;
            int row = (mat < 1) ? (bm + r) : (bn + r);
            CP_ASYNC16(dst, srcs[mat] + (size_t)row * DMODEL + seg * 8);
        }
    }
    CP_COMMIT();

    for (int it = 0; it < 32; it++) {
        CP_WAIT0();
        __syncthreads();
        if (it + 1 < 32) {
            const int k0 = (it + 1) * 32;
            const uint32_t stg = sb + ((it + 1) & 1) * G_STAGE;
            #pragma unroll
            for (int i = 0; i < 6; i++) {
                int c = tid + i * 256;
                int mat = c >> 9, r = (c >> 2) & 127, seg = c & 3;
                if (mat != 2 || np == 2) {
                    uint32_t dst = stg + mat * G_MAT + r * G_STRIDE + seg * 16;
                    int row = (mat < 1) ? (bm + r) : (bn + r);
                    CP_ASYNC16(dst, srcs[mat] + (size_t)row * DMODEL + k0 + seg * 8);
                }
            }
            CP_COMMIT();
        }

        const uint32_t stg = sb + (it & 1) * G_STAGE;
        const uint32_t aRow = warpM + (lane & 15);
        #pragma unroll
        for (int ks = 0; ks < 2; ks++) {
            const uint32_t kOffA = (ks * 16 + 8 * (lane >> 4)) * 2;
            const uint32_t kOffB = (ks * 16 + 8 * ((lane >> 3) & 1)) * 2;
            uint32_t ah[4][4];
            #pragma unroll
            for (int mi = 0; mi < 4; mi++) {
                uint32_t ad = stg + (aRow + mi * 16) * G_STRIDE + kOffA;
                LDSM_X4(ah[mi][0], ah[mi][1], ah[mi][2], ah[mi][3], ad);
            }
            #pragma unroll
            for (int nj = 0; nj < 4; nj += 2) {
                uint32_t bd = stg + G_MAT
                            + (warpN + (nj + (lane >> 4)) * 8 + (lane & 7)) * G_STRIDE + kOffB;
                uint32_t bh0, bh1, bh2, bh3;
                LDSM_X4(bh0, bh1, bh2, bh3, bd);
                #pragma unroll
                for (int mi = 0; mi < 4; mi++) {
                    mma_f16(acc[mi][nj], ah[mi][0], ah[mi][1], ah[mi][2], ah[mi][3], bh0, bh1);
                    mma_f16(acc[mi][nj + 1], ah[mi][0], ah[mi][1], ah[mi][2], ah[mi][3], bh2, bh3);
                }
                if (np == 2) {
                    uint32_t bl0, bl1, bl2, bl3;
                    LDSM_X4(bl0, bl1, bl2, bl3, bd + G_MAT);
                    #pragma unroll
                    for (int mi = 0; mi < 4; mi++) {
                        mma_f16(acc[mi][nj], ah[mi][0], ah[mi][1], ah[mi][2], ah[mi][3], bl0, bl1);
                        mma_f16(acc[mi][nj + 1], ah[mi][0], ah[mi][1], ah[mi][2], ah[mi][3], bl2, bl3);
                    }
                }
            }
        }
    }

    // epilogue
    #pragma unroll
    for (int mi = 0; mi < 4; mi++) {
        #pragma unroll
        for (int nj = 0; nj < 4; nj++) {
            int n = bn + warpN + nj * 8 + 2 * (lane & 3);
            float bias0 = bias[n], bias1 = bias[n + 1];
            #pragma unroll
            for (int half = 0; half < 2; half++) {
                int m = bm + warpM + mi * 16 + (lane >> 2) + half * 8;
                float v0 = acc[mi][nj][half * 2 + 0] + bias0;
                float v1 = acc[mi][nj][half * 2 + 1] + bias1;
                if (mode == 0) {
                    float2 o; o.x = v0; o.y = v1;
                    *(float2*)&ga.outF[z][(size_t)m * DMODEL + n] = o;
                } else {
                    int b = m >> 11, l = m & 2047;
                    int h = n >> 6, d = n & 63;
                    size_t idx = (((size_t)(b * NH + h)) * LL + l) * DK + d;
                    if (mode == 1) {
                        __nv_bfloat16 h0, h1, l0, l1;
                        split2(v0, h0, l0); split2(v1, h1, l1);
                        store_bf2(&ga.oh[z][idx], h0, h1);
                        store_bf2(&ga.ol[z][idx], l0, l1);
                    } else {
                        store_h2(&ga.ohf[z][idx], __float2half_rn(v0), __float2half_rn(v1));
                    }
                }
            }
        }
    }
}

// ---------------------------------------------------------------------------
// Flash attention, ONLINE softmax, 2-stage cp.async.
// CTA: 128 queries x one (b,h); 32 key tiles of 64; 8 warps, warp = 16 queries.
// S = bf16 3-pass. P = single fp16 (p = exp(s - m) <= 1).
// P·V = fp16 1-PASS (V single fp16) via mma_f16 + ldmatrix.trans.
// ---------------------------------------------------------------------------
#define A_KSTRIDE 144           // 64 elems * 2B + 16 pad
#define A_KMAT    9216          // 64*144
#define A_VOFF    18432         // 2*A_KMAT (V single follows K hi/lo)
#define A_STAGE   27648         // 3 mats * 9216
#define ATTN_SMEM (2 * A_STAGE) // 55296

__global__ __launch_bounds__(256, 2) void attn_mma(
    const __nv_bfloat16* __restrict__ Qh, const __nv_bfloat16* __restrict__ Ql,
    const __nv_bfloat16* __restrict__ Kh, const __nv_bfloat16* __restrict__ Kl,
    const __half* __restrict__ Vf,
    __half* __restrict__ Cf)
{
    extern __shared__ char smem[];
    const uint32_t sb = smem_u32(smem);
    const int tid = threadIdx.x, wid = tid >> 5, lane = tid & 31;
    const int bh = blockIdx.y, q0 = blockIdx.x * 128;
    const int warpM = wid * 16;

    const __nv_bfloat16* qbh = Qh + (size_t)bh * LL * DK;
    const __nv_bfloat16* qbl = Ql + (size_t)bh * LL * DK;
    const __nv_bfloat16* srcs[3] = {
        Kh + (size_t)bh * LL * DK, Kl + (size_t)bh * LL * DK,
        (const __nv_bfloat16*)(Vf + (size_t)bh * LL * DK)};

    // ---- Q preload into smem, extract fragments, reuse ----
    #pragma unroll
    for (int i = 0; i < 8; i++) {
        int c = tid + i * 256;                 // 2048 chunks: 2 mats x 128 rows x 8 segs
        int mat = c >> 10, r = (c >> 3) & 127, seg = c & 7;
        const __nv_bfloat16* src = (mat ? qbl : qbh) + (size_t)(q0 + r) * DK + seg * 8;
        *(uint4*)(smem + mat * 18432 + r * A_KSTRIDE + seg * 16) = *(const uint4*)src;
    }
    __syncthreads();
    uint32_t qh[4][4], ql[4][4];
    {
        const uint32_t aRow = warpM + (lane & 15);
        #pragma unroll
        for (int ks = 0; ks < 4; ks++) {
            uint32_t ad = sb + aRow * A_KSTRIDE + (ks * 16 + 8 * (lane >> 4)) * 2;
            LDSM_X4(qh[ks][0], qh[ks][1], qh[ks][2], qh[ks][3], ad);
            LDSM_X4(ql[ks][0], ql[ks][1], ql[ks][2], ql[ks][3], ad + 18432);
        }
    }
    __syncthreads();

    // ---- K/V prologue: tile 0 -> stage 0 (3 mats x 64 rows x 8 segs = 1536) ----
    #pragma unroll
    for (int i = 0; i < 6; i++) {
        int c = tid + i * 256;
        int mat = c >> 9, r = (c >> 3) & 63, seg = c & 7;
        uint32_t dst = sb + mat * A_KMAT + r * A_KSTRIDE + seg * 16;
        CP_ASYNC16(dst, srcs[mat] + (size_t)r * DK + seg * 8);
    }
    CP_COMMIT();

    float Oacc[8][4];
    #pragma unroll
    for (int j = 0; j < 8; j++)
        #pragma unroll
        for (int r = 0; r < 4; r++) Oacc[j][r] = 0.0f;
    float rowsum0 = 0.0f, rowsum1 = 0.0f;
    float m0 = -INFINITY, m1 = -INFINITY;

    const int row0 = q0 + warpM + (lane >> 2);
    const int dc = 2 * (lane & 3);

    for (int kt = 0; kt < 32; kt++) {
        // mask bits (gmem; overlap with wait)
        uint32_t mw0[2], mw1[2];
        #pragma unroll
        for (int w = 0; w < 2; w++) {
            mw0[w] = g_maskbits[(size_t)row0 * MASK_W + kt * 2 + w];
            mw1[w] = g_maskbits[(size_t)(row0 + 8) * MASK_W + kt * 2 + w];
        }

        CP_WAIT0();
        __syncthreads();
        if (kt + 1 < 32) {
            const int kbase = (kt + 1) * 64;
            const uint32_t stg = sb + ((kt + 1) & 1) * A_STAGE;
            #pragma unroll
            for (int i = 0; i < 6; i++) {
                int c = tid + i * 256;
                int mat = c >> 9, r = (c >> 3) & 63, seg = c & 7;
                uint32_t dst = stg + mat * A_KMAT + r * A_KSTRIDE + seg * 16;
                CP_ASYNC16(dst, srcs[mat] + (size_t)(kbase + r) * DK + seg * 8);
            }
            CP_COMMIT();
        }

        const uint32_t stg = sb + (kt & 1) * A_STAGE;

        // ---- S = Q K^T (bf16 3-pass) ----
        float Sacc[8][4];
        #pragma unroll
        for (int j = 0; j < 8; j++)
            #pragma unroll
            for (int r = 0; r < 4; r++) Sacc[j][r] = 0.0f;

        #pragma unroll
        for (int ks = 0; ks < 4; ks++) {
            const uint32_t kOffB = (ks * 16 + 8 * ((lane >> 3) & 1)) * 2;
            #pragma unroll
            for (int j = 0; j < 8; j += 2) {
                uint32_t bd = stg + ((j + (lane >> 4)) * 8 + (lane & 7)) * A_KSTRIDE + kOffB;
                uint32_t bh0, bh1, bh2, bh3, bl0, bl1, bl2, bl3;
                LDSM_X4(bh0, bh1, bh2, bh3, bd);
                LDSM_X4(bl0, bl1, bl2, bl3, bd + A_KMAT);
                mma_bf16(Sacc[j], qh[ks][0], qh[ks][1], qh[ks][2], qh[ks][3], bh0, bh1);
                mma_bf16(Sacc[j], qh[ks][0], qh[ks][1], qh[ks][2], qh[ks][3], bl0, bl1);
                mma_bf16(Sacc[j], ql[ks][0], ql[ks][1], ql[ks][2], ql[ks][3], bh0, bh1);
                mma_bf16(Sacc[j + 1], qh[ks][0], qh[ks][1], qh[ks][2], qh[ks][3], bh2, bh3);
                mma_bf16(Sacc[j + 1], qh[ks][0], qh[ks][1], qh[ks][2], qh[ks][3], bl2, bl3);
                mma_bf16(Sacc[j + 1], ql[ks][0], ql[ks][1], ql[ks][2], ql[ks][3], bh2, bh3);
            }
        }

        // ---- apply mask (s -> -inf) + tile row max ----
        float tmax0 = -INFINITY, tmax1 = -INFINITY;
        #pragma unroll
        for (int j = 0; j < 8; j++) {
            const int sh = (j & 3) * 8 + dc;
            uint32_t b0 = (mw0[j >> 2] >> sh) & 3u;
            uint32_t b1 = (mw1[j >> 2] >> sh) & 3u;
            if (b0 & 1u) Sacc[j][0] = -INFINITY;
            if (b0 & 2u) Sacc[j][1] = -INFINITY;
            if (b1 & 1u) Sacc[j][2] = -INFINITY;
            if (b1 & 2u) Sacc[j][3] = -INFINITY;
            tmax0 = fmaxf(tmax0, fmaxf(Sacc[j][0], Sacc[j][1]));
            tmax1 = fmaxf(tmax1, fmaxf(Sacc[j][2], Sacc[j][3]));
        }
        tmax0 = fmaxf(tmax0, __shfl_xor_sync(0xFFFFFFFFu, tmax0, 1));
        tmax0 = fmaxf(tmax0, __shfl_xor_sync(0xFFFFFFFFu, tmax0, 2));
        tmax1 = fmaxf(tmax1, __shfl_xor_sync(0xFFFFFFFFu, tmax1, 1));
        tmax1 = fmaxf(tmax1, __shfl_xor_sync(0xFFFFFFFFu, tmax1, 2));
        if (tmax0 > m0) {
            float sc = __expf(m0 - tmax0);   // m0=-inf -> 0; Oacc/rowsum were 0
            rowsum0 *= sc;
            #pragma unroll
            for (int dj = 0; dj < 8; dj++) { Oacc[dj][0] *= sc; Oacc[dj][1] *= sc; }
            m0 = tmax0;
        }
        if (tmax1 > m1) {
            float sc = __expf(m1 - tmax1);
            rowsum1 *= sc;
            #pragma unroll
            for (int dj = 0; dj < 8; dj++) { Oacc[dj][2] *= sc; Oacc[dj][3] *= sc; }
            m1 = tmax1;
        }
        const float mm0 = (m0 == -INFINITY) ? 0.0f : m0;
        const float mm1 = (m1 == -INFINITY) ? 0.0f : m1;

        // ---- p = exp(s - m) in fp16, P·V (1-pass fp16, V single via trans) ----
        #pragma unroll
        for (int s = 0; s < 4; s++) {
            uint32_t pa[4];
            #pragma unroll
            for (int h2 = 0; h2 < 2; h2++) {
                const int j = 2 * s + h2;
                float p0 = __expf(Sacc[j][0] - mm0);   // masked: exp(-inf)=0
                float p1 = __expf(Sacc[j][1] - mm0);
                float p2 = __expf(Sacc[j][2] - mm1);
                float p3 = __expf(Sacc[j][3] - mm1);
                __half h0 = __float2half_rn(p0);
                __half h1 = __float2half_rn(p1);
                __half h2b = __float2half_rn(p2);
                __half h3 = __float2half_rn(p3);
                rowsum0 += __half2float(h0) + __half2float(h1);
                rowsum1 += __half2float(h2b) + __half2float(h3);
                pa[h2 * 2 + 0] = pack_h2(h0, h1);
                pa[h2 * 2 + 1] = pack_h2(h2b, h3);
            }
            // V fragments: rows = keys (s*16 + k), cols = d; trans-load
            const uint32_t vrow = (s * 16 + (lane & 7) + 8 * ((lane >> 3) & 1));
            #pragma unroll
            for (int dj = 0; dj < 8; dj += 2) {
                uint32_t vd = stg + A_VOFF + vrow * A_KSTRIDE + (dj * 8 + 8 * (lane >> 4)) * 2;
                uint32_t vh0, vh1, vh2, vh3;
                LDSM_X4_T(vh0, vh1, vh2, vh3, vd);
                mma_f16(Oacc[dj], pa[0], pa[1], pa[2], pa[3], vh0, vh1);
                mma_f16(Oacc[dj + 1], pa[0], pa[1], pa[2], pa[3], vh2, vh3);
            }
        }
    }

    // row-sum reduce across the 4 threads sharing a row
    rowsum0 += __shfl_xor_sync(0xFFFFFFFFu, rowsum0, 1);
    rowsum0 += __shfl_xor_sync(0xFFFFFFFFu, rowsum0, 2);
    rowsum1 += __shfl_xor_sync(0xFFFFFFFFu, rowsum1, 1);
    rowsum1 += __shfl_xor_sync(0xFFFFFFFFu, rowsum1, 2);
    const float inv0 = (rowsum0 > 0.0f) ? (1.0f / rowsum0) : 0.0f;
    const float inv1 = (rowsum1 > 0.0f) ? (1.0f / rowsum1) : 0.0f;

    const int b = bh >> 4, h = bh & 15;
    #pragma unroll
    for (int dj = 0; dj < 8; dj++) {
        int d = h * DK + dj * 8 + dc;
        {
            float v0 = Oacc[dj][0] * inv0, v1 = Oacc[dj][1] * inv0;
            size_t idx = ((size_t)(b * LL + row0)) * DMODEL + d;
            store_h2(&Cf[idx], __float2half_rn(v0), __float2half_rn(v1));
        }
        {
            float v0 = Oacc[dj][2] * inv1, v1 = Oacc[dj][3] * inv1;
            size_t idx = ((size_t)(b * LL + row0 + 8)) * DMODEL + d;
            store_h2(&Cf[idx], __float2half_rn(v0), __float2half_rn(v1));
        }
    }
}

// ---------------------------------------------------------------------------
// Launch
// ---------------------------------------------------------------------------
extern "C" void kernel_launch(void* const* d_in, const int* in_sizes, int n_in,
                              void* d_out, int out_size) {
    (void)in_sizes; (void)n_in; (void)out_size;
    const float* query = (const float*)d_in[0];
    const float* key   = (const float*)d_in[1];
    const float* value = (const float*)d_in[2];
    const void*  mask  = d_in[3];
    const float* W_q = (const float*)d_in[4];
    const float* b_q = (const float*)d_in[5];
    const float* W_k = (const float*)d_in[6];
    const float* b_k = (const float*)d_in[7];
    const float* W_v = (const float*)d_in[8];
    const float* b_v = (const float*)d_in[9];
    const float* W_o = (const float*)d_in[10];
    const float* b_o = (const float*)d_in[11];

    __half *in_q, *in_k, *in_v;
    __half *w_qh, *w_ql, *w_kh, *w_kl, *w_vh, *w_vl, *w_oh, *w_ol;
    __half *Vfp, *Cfp;
    __nv_bfloat16 *Qh, *Qlp, *Kh, *Klp;
    cudaGetSymbolAddress((void**)&in_q, g_in_q);
    cudaGetSymbolAddress((void**)&in_k, g_in_k);
    cudaGetSymbolAddress((void**)&in_v, g_in_v);
    cudaGetSymbolAddress((void**)&w_qh, g_w_qh);   cudaGetSymbolAddress((void**)&w_ql, g_w_ql);
    cudaGetSymbolAddress((void**)&w_kh, g_w_kh);   cudaGetSymbolAddress((void**)&w_kl, g_w_kl);
    cudaGetSymbolAddress((void**)&w_vh, g_w_vh);   cudaGetSymbolAddress((void**)&w_vl, g_w_vl);
    cudaGetSymbolAddress((void**)&w_oh, g_w_oh);   cudaGetSymbolAddress((void**)&w_ol, g_w_ol);
    cudaGetSymbolAddress((void**)&Qh, g_Qh);   cudaGetSymbolAddress((void**)&Qlp, g_Ql);
    cudaGetSymbolAddress((void**)&Kh, g_Kh);   cudaGetSymbolAddress((void**)&Klp, g_Kl);
    cudaGetSymbolAddress((void**)&Vfp, g_Vf);
    cudaGetSymbolAddress((void**)&Cfp, g_Cf);

    cudaFuncSetAttribute(mma_gemm, cudaFuncAttributeMaxDynamicSharedMemorySize, GEMM_SMEM);
    cudaFuncSetAttribute(attn_mma, cudaFuncAttributeMaxDynamicSharedMemorySize, ATTN_SMEM);

    // Fused prep: mask bits + q/k/v fp16 convert + weight transpose/split
    PrepArgs pa;
    pa.mask = mask;
    pa.q = (const float4*)query; pa.k = (const float4*)key; pa.v = (const float4*)value;
    pa.oq = (__half2*)in_q; pa.ok = (__half2*)in_k; pa.ov = (__half2*)in_v;
    pa.wq = W_q; pa.wk = W_k; pa.wv = W_v; pa.wo = W_o;
    pa.wqh = w_qh; pa.wql = w_ql; pa.wkh = w_kh; pa.wkl = w_kl;
    pa.wvh = w_vh; pa.wvl = w_vl; pa.woh = w_oh; pa.wol = w_ol;
    prep_kernel<<<PREP_TOTAL, 256>>>(pa);

    // Fused Q/K/V projections: grid.z = 3
    // Q,K: 2-pass, bf16 hi/lo out. V: 1-pass, fp16 single out.
    GArgs gp = {};
    gp.A[0] = in_q; gp.Bh[0] = w_qh; gp.Bl[0] = w_ql;
    gp.bias[0] = b_q; gp.oh[0] = Qh;  gp.ol[0] = Qlp; gp.mode[0] = 1; gp.np[0] = 2;
    gp.A[1] = in_k; gp.Bh[1] = w_kh; gp.Bl[1] = w_kl;
    gp.bias[1] = b_k; gp.oh[1] = Kh;  gp.ol[1] = Klp; gp.mode[1] = 1; gp.np[1] = 2;
    gp.A[2] = in_v; gp.Bh[2] = w_vh; gp.Bl[2] = w_vl;
    gp.bias[2] = b_v; gp.ohf[2] = Vfp; gp.mode[2] = 3; gp.np[2] = 1;
    dim3 gg3(DMODEL / 128, MROWS / 128, 3);   // (8, 32, 3)
    mma_gemm<<<gg3, 256, GEMM_SMEM>>>(gp);

    dim3 ag(LL / 128, BB * NH);               // (16, 32)
    attn_mma<<<ag, 256, ATTN_SMEM>>>(Qh, Qlp, Kh, Klp, Vfp, Cfp);

    // Output projection (A = attention output in single fp16; 2-pass W)
    GArgs go = {};
    go.A[0] = Cfp; go.Bh[0] = w_oh; go.Bl[0] = w_ol;
    go.bias[0] = b_o; go.outF[0] = (float*)d_out; go.mode[0] = 0; go.np[0] = 2;
    dim3 gg1(DMODEL / 128, MROWS / 128, 1);   // (8, 32, 1)
    mma_gemm<<<gg1, 256, GEMM_SMEM>>>(go);
}

// round 15
// speedup vs baseline: 1.3589x; 1.1483x over previous
#include <cuda_runtime.h>
#include <cuda_bf16.h>
#include <cuda_fp16.h>
#include <math.h>
#include <stdint.h>

// Problem constants
#define BB 2
#define LL 2048
#define DMODEL 1024
#define NH 16
#define DK 64
#define MROWS (BB * LL)          // 4096
#define MASK_W (LL / 32)         // 64 words per row
#define MASK_WORDS (LL * MASK_W)

// ---------------------------------------------------------------------------
// Device scratch (no allocations allowed)
// ---------------------------------------------------------------------------
__device__ __half g_in_q[MROWS * DMODEL], g_in_k[MROWS * DMODEL], g_in_v[MROWS * DMODEL];
__device__ __half g_w_qh[DMODEL * DMODEL], g_w_ql[DMODEL * DMODEL];
__device__ __half g_w_kh[DMODEL * DMODEL], g_w_kl[DMODEL * DMODEL];
__device__ __half g_w_vh[DMODEL * DMODEL], g_w_vl[DMODEL * DMODEL];
__device__ __half g_w_oh[DMODEL * DMODEL], g_w_ol[DMODEL * DMODEL];
__device__ __half g_Qf[MROWS * DMODEL];                                // [b,h,l,d] fp16 single
__device__ __half g_Kfh[MROWS * DMODEL], g_Kfl[MROWS * DMODEL];        // [b,h,l,d] fp16 hi/lo
__device__ __half g_Vf[MROWS * DMODEL];                                // [b,h,l,d] fp16 single
__device__ __half g_Cf[MROWS * DMODEL];                                // [b,l,dmodel] fp16
__device__ unsigned int g_maskbits[MASK_WORDS];

// ---------------------------------------------------------------------------
// PTX helpers (portable PTX only: mma.sync / ldmatrix / cp.async)
// ---------------------------------------------------------------------------
__device__ __forceinline__ uint32_t smem_u32(const void* p) {
    uint32_t a;
    asm("{ .reg .u64 t; cvta.to.shared.u64 t, %1; cvt.u32.u64 %0, t; }" : "=r"(a) : "l"(p));
    return a;
}

#define CP_ASYNC16(dst, src) \
    asm volatile("cp.async.cg.shared.global [%0], [%1], 16;" :: "r"(dst), "l"(src))
#define CP_COMMIT() asm volatile("cp.async.commit_group;" ::: "memory")
#define CP_WAIT0()  asm volatile("cp.async.wait_group 0;" ::: "memory")

#define LDSM_X4(r0, r1, r2, r3, addr) \
    asm volatile("ldmatrix.sync.aligned.m8n8.x4.shared.b16 {%0,%1,%2,%3}, [%4];" \
        : "=r"(r0), "=r"(r1), "=r"(r2), "=r"(r3) : "r"(addr))
#define LDSM_X4_T(r0, r1, r2, r3, addr) \
    asm volatile("ldmatrix.sync.aligned.m8n8.x4.trans.shared.b16 {%0,%1,%2,%3}, [%4];" \
        : "=r"(r0), "=r"(r1), "=r"(r2), "=r"(r3) : "r"(addr))

__device__ __forceinline__ void mma_f16(float* c, uint32_t a0, uint32_t a1, uint32_t a2, uint32_t a3,
                                        uint32_t b0, uint32_t b1) {
    asm volatile("mma.sync.aligned.m16n8k16.row.col.f32.f16.f16.f32 "
        "{%0,%1,%2,%3}, {%4,%5,%6,%7}, {%8,%9}, {%0,%1,%2,%3};"
        : "+f"(c[0]), "+f"(c[1]), "+f"(c[2]), "+f"(c[3])
        : "r"(a0), "r"(a1), "r"(a2), "r"(a3), "r"(b0), "r"(b1));
}

__device__ __forceinline__ void split2h(float x, __half& h, __half& l) {
    h = __float2half_rn(x);
    l = __float2half_rn(x - __half2float(h));
}
__device__ __forceinline__ uint32_t pack_h2(__half e0, __half e1) {
    __half2 t; t.x = e0; t.y = e1;
    return *(uint32_t*)&t;
}
__device__ __forceinline__ void store_h2(__half* p, __half e0, __half e1) {
    __half2 t; t.x = e0; t.y = e1;
    *(__half2*)p = t;
}

// ---------------------------------------------------------------------------
// Fused prep kernel: blockIdx.x ranges select mask / conv3 / transpose work.
// ---------------------------------------------------------------------------
#define PREP_MASK_CTAS 512
#define PREP_CONV_CTAS 4096
#define PREP_TR_CTAS   1024
#define PREP_TOTAL (PREP_MASK_CTAS + 3 * PREP_CONV_CTAS + 4 * PREP_TR_CTAS)

struct PrepArgs {
    const void* mask;
    const float4 *q, *k, *v;
    __half2 *oq, *ok, *ov;
    const float *wq, *wk, *wv, *wo;
    __half *wqh, *wql, *wkh, *wkl, *wvh, *wvl, *woh, *wol;
};

__global__ __launch_bounds__(256) void prep_kernel(PrepArgs pa) {
    const int cta = blockIdx.x, tid = threadIdx.x;
    if (cta < PREP_MASK_CTAS) {
        const unsigned int* w = (const unsigned int*)pa.mask;
        bool all_i32 = true, all_f32 = true;
        #pragma unroll
        for (int i = 0; i < 64; i++) {
            unsigned int v = w[i];
            if (v > 1u) all_i32 = false;
            if (v != 0u && v != 0x3F800000u) all_f32 = false;
        }
        int idx = cta * 256 + tid;
        size_t base = (size_t)idx * 32;
        uint32_t bits = 0;
        if (all_i32 || all_f32) {
            const uint4* p = (const uint4*)((const unsigned int*)pa.mask + base);
            #pragma unroll
            for (int g = 0; g < 8; g++) {
                uint4 v = p[g];
                bits |= (v.x != 0u ? 1u : 0u) << (g * 4 + 0);
                bits |= (v.y != 0u ? 1u : 0u) << (g * 4 + 1);
                bits |= (v.z != 0u ? 1u : 0u) << (g * 4 + 2);
                bits |= (v.w != 0u ? 1u : 0u) << (g * 4 + 3);
            }
        } else {
            const uchar4* p = (const uchar4*)((const unsigned char*)pa.mask + base);
            #pragma unroll
            for (int g = 0; g < 8; g++) {
                uchar4 v = p[g];
                bits |= (v.x ? 1u : 0u) << (g * 4 + 0);
                bits |= (v.y ? 1u : 0u) << (g * 4 + 1);
                bits |= (v.z ? 1u : 0u) << (g * 4 + 2);
                bits |= (v.w ? 1u : 0u) << (g * 4 + 3);
            }
        }
        g_maskbits[idx] = bits;
    } else if (cta < PREP_MASK_CTAS + 3 * PREP_CONV_CTAS) {
        int rel = cta - PREP_MASK_CTAS;
        int which = rel / PREP_CONV_CTAS, blk = rel % PREP_CONV_CTAS;
        const float4* in = (which == 0) ? pa.q : (which == 1) ? pa.k : pa.v;
        __half2* out = (which == 0) ? pa.oq : (which == 1) ? pa.ok : pa.ov;
        int i = blk * 256 + tid;
        float4 vv = in[i];
        __half2 a, b;
        a.x = __float2half_rn(vv.x); a.y = __float2half_rn(vv.y);
        b.x = __float2half_rn(vv.z); b.y = __float2half_rn(vv.w);
        out[i * 2] = a;
        out[i * 2 + 1] = b;
    } else {
        int rel = cta - PREP_MASK_CTAS - 3 * PREP_CONV_CTAS;
        int which = rel / PREP_TR_CTAS, tile = rel % PREP_TR_CTAS;
        const float* in = (which == 0) ? pa.wq : (which == 1) ? pa.wk : (which == 2) ? pa.wv : pa.wo;
        __half* hi = (which == 0) ? pa.wqh : (which == 1) ? pa.wkh : (which == 2) ? pa.wvh : pa.woh;
        __half* lo = (which == 0) ? pa.wql : (which == 1) ? pa.wkl : (which == 2) ? pa.wvl : pa.wol;
        __shared__ float t[32][33];
        int n0 = (tile & 31) * 32, k0 = (tile >> 5) * 32;
        int c = tid & 31, r0 = tid >> 5;
        #pragma unroll
        for (int p = 0; p < 4; p++) {
            int r = r0 + p * 8;
            t[r][c] = in[(size_t)(k0 + r) * DMODEL + n0 + c];
        }
        __syncthreads();
        #pragma unroll
        for (int p = 0; p < 4; p++) {
            int r = r0 + p * 8;
            float v = t[c][r];
            int n = n0 + r, k = k0 + c;
            __half h, l;
            split2h(v, h, l);
            hi[(size_t)n * DMODEL + k] = h;
            lo[(size_t)n * DMODEL + k] = l;
        }
    }
}

// ---------------------------------------------------------------------------
// GEMM (fp16): C[m][n] = sum_k A[m,k]*W[n,k] + bias[n]
// np=2: W = Wh + Wl (2-pass). np=1: W = Wh only (1-pass).
// mode 0: fp32 out; 2: fp16 hi/lo [b,h,l,d]; 3: fp16 single [b,h,l,d].
// ---------------------------------------------------------------------------
#define G_STRIDE 80
#define G_MAT    10240          // 128*80
#define G_STAGE  30720          // 3 mats
#define GEMM_SMEM (2 * G_STAGE) // 61440

struct GArgs {
    const __half *A[3], *Bh[3], *Bl[3];
    const float* bias[3];
    float* outF[3];
    __half *ohf[3], *olf[3];
    int mode[3];
    int np[3];
};

__global__ __launch_bounds__(256, 2) void mma_gemm(GArgs ga)
{
    extern __shared__ char smem[];
    const uint32_t sb = smem_u32(smem);
    const int z = blockIdx.z;
    const __half* __restrict__ A  = ga.A[z];
    const __half* __restrict__ Bh = ga.Bh[z];
    const __half* __restrict__ Bl = ga.Bl[z];
    const float* __restrict__ bias = ga.bias[z];
    const int mode = ga.mode[z];
    const int np = ga.np[z];

    const int tid = threadIdx.x, wid = tid >> 5, lane = tid & 31;
    const int bm = blockIdx.y * 128, bn = blockIdx.x * 128;
    const int warpM = (wid >> 2) * 64, warpN = (wid & 3) * 32;

    float acc[4][4][4];
    #pragma unroll
    for (int i = 0; i < 4; i++)
        #pragma unroll
        for (int j = 0; j < 4; j++)
            #pragma unroll
            for (int r = 0; r < 4; r++) acc[i][j][r] = 0.0f;

    const __half* srcs[3] = {A, Bh, Bl};

    // prologue: tile 0 -> stage 0
    #pragma unroll
    for (int i = 0; i < 6; i++) {
        int c = tid + i * 256;
        int mat = c >> 9, r = (c >> 2) & 127, seg = c & 3;
        if (mat != 2 || np == 2) {
            uint32_t dst = sb + mat * G_MAT + r * G_STRIDE + seg * 16;
            int row = (mat < 1) ? (bm + r) : (bn + r);
            CP_ASYNC16(dst, srcs[mat] + (size_t)row * DMODEL + seg * 8);
        }
    }
    CP_COMMIT();

    for (int it = 0; it < 32; it++) {
        CP_WAIT0();
        __syncthreads();
        if (it + 1 < 32) {
            const int k0 = (it + 1) * 32;
            const uint32_t stg = sb + ((it + 1) & 1) * G_STAGE;
            #pragma unroll
            for (int i = 0; i < 6; i++) {
                int c = tid + i * 256;
                int mat = c >> 9, r = (c >> 2) & 127, seg = c & 3;
                if (mat != 2 || np == 2) {
                    uint32_t dst = stg + mat * G_MAT + r * G_STRIDE + seg * 16;
                    int row = (mat < 1) ? (bm + r) : (bn + r);
                    CP_ASYNC16(dst, srcs[mat] + (size_t)row * DMODEL + k0 + seg * 8);
                }
            }
            CP_COMMIT();
        }

        const uint32_t stg = sb + (it & 1) * G_STAGE;
        const uint32_t aRow = warpM + (lane & 15);
        #pragma unroll
        for (int ks = 0; ks < 2; ks++) {
            const uint32_t kOffA = (ks * 16 + 8 * (lane >> 4)) * 2;
            const uint32_t kOffB = (ks * 16 + 8 * ((lane >> 3) & 1)) * 2;
            uint32_t ah[4][4];
            #pragma unroll
            for (int mi = 0; mi < 4; mi++) {
                uint32_t ad = stg + (aRow + mi * 16) * G_STRIDE + kOffA;
                LDSM_X4(ah[mi][0], ah[mi][1], ah[mi][2], ah[mi][3], ad);
            }
            #pragma unroll
            for (int nj = 0; nj < 4; nj += 2) {
                uint32_t bd = stg + G_MAT
                            + (warpN + (nj + (lane >> 4)) * 8 + (lane & 7)) * G_STRIDE + kOffB;
                uint32_t bh0, bh1, bh2, bh3;
                LDSM_X4(bh0, bh1, bh2, bh3, bd);
                #pragma unroll
                for (int mi = 0; mi < 4; mi++) {
                    mma_f16(acc[mi][nj], ah[mi][0], ah[mi][1], ah[mi][2], ah[mi][3], bh0, bh1);
                    mma_f16(acc[mi][nj + 1], ah[mi][0], ah[mi][1], ah[mi][2], ah[mi][3], bh2, bh3);
                }
                if (np == 2) {
                    uint32_t bl0, bl1, bl2, bl3;
                    LDSM_X4(bl0, bl1, bl2, bl3, bd + G_MAT);
                    #pragma unroll
                    for (int mi = 0; mi < 4; mi++) {
                        mma_f16(acc[mi][nj], ah[mi][0], ah[mi][1], ah[mi][2], ah[mi][3], bl0, bl1);
                        mma_f16(acc[mi][nj + 1], ah[mi][0], ah[mi][1], ah[mi][2], ah[mi][3], bl2, bl3);
                    }
                }
            }
        }
    }

    // epilogue
    #pragma unroll
    for (int mi = 0; mi < 4; mi++) {
        #pragma unroll
        for (int nj = 0; nj < 4; nj++) {
            int n = bn + warpN + nj * 8 + 2 * (lane & 3);
            float bias0 = bias[n], bias1 = bias[n + 1];
            #pragma unroll
            for (int half = 0; half < 2; half++) {
                int m = bm + warpM + mi * 16 + (lane >> 2) + half * 8;
                float v0 = acc[mi][nj][half * 2 + 0] + bias0;
                float v1 = acc[mi][nj][half * 2 + 1] + bias1;
                if (mode == 0) {
                    float2 o; o.x = v0; o.y = v1;
                    *(float2*)&ga.outF[z][(size_t)m * DMODEL + n] = o;
                } else {
                    int b = m >> 11, l = m & 2047;
                    int h = n >> 6, d = n & 63;
                    size_t idx = (((size_t)(b * NH + h)) * LL + l) * DK + d;
                    if (mode == 2) {
                        __half h0, h1, l0, l1;
                        split2h(v0, h0, l0); split2h(v1, h1, l1);
                        store_h2(&ga.ohf[z][idx], h0, h1);
                        store_h2(&ga.olf[z][idx], l0, l1);
                    } else {
                        store_h2(&ga.ohf[z][idx], __float2half_rn(v0), __float2half_rn(v1));
                    }
                }
            }
        }
    }
}

// ---------------------------------------------------------------------------
// Flash attention, ONLINE softmax, 2-stage cp.async.
// CTA: 128 queries x one (b,h); 32 key tiles of 64; 8 warps, warp = 16 queries.
// S = fp16 2-PASS: Q single fp16 x K fp16 hi/lo (64 MMAs/tile).
// P = single fp16 (p = exp(s - m) <= 1). P·V = fp16 1-pass (32 MMAs/tile).
// ---------------------------------------------------------------------------
#define A_KSTRIDE 144           // 64 elems * 2B + 16 pad
#define A_KMAT    9216          // 64*144
#define A_VOFF    18432         // 2*A_KMAT (V single follows K hi/lo)
#define A_STAGE   27648         // 3 mats * 9216
#define ATTN_SMEM (2 * A_STAGE) // 55296

__global__ __launch_bounds__(256, 2) void attn_mma(
    const __half* __restrict__ Qf,
    const __half* __restrict__ Kfh, const __half* __restrict__ Kfl,
    const __half* __restrict__ Vf,
    __half* __restrict__ Cf)
{
    extern __shared__ char smem[];
    const uint32_t sb = smem_u32(smem);
    const int tid = threadIdx.x, wid = tid >> 5, lane = tid & 31;
    const int bh = blockIdx.y, q0 = blockIdx.x * 128;
    const int warpM = wid * 16;

    const __half* qbf = Qf + (size_t)bh * LL * DK;
    const __half* srcs[3] = {
        Kfh + (size_t)bh * LL * DK, Kfl + (size_t)bh * LL * DK,
        Vf + (size_t)bh * LL * DK};

    // ---- Q preload (single fp16): 128 rows x 8 segs = 1024 chunks ----
    #pragma unroll
    for (int i = 0; i < 4; i++) {
        int c = tid + i * 256;
        int r = c >> 3, seg = c & 7;
        const __half* src = qbf + (size_t)(q0 + r) * DK + seg * 8;
        *(uint4*)(smem + r * A_KSTRIDE + seg * 16) = *(const uint4*)src;
    }
    __syncthreads();
    uint32_t qf[4][4];
    {
        const uint32_t aRow = warpM + (lane & 15);
        #pragma unroll
        for (int ks = 0; ks < 4; ks++) {
            uint32_t ad = sb + aRow * A_KSTRIDE + (ks * 16 + 8 * (lane >> 4)) * 2;
            LDSM_X4(qf[ks][0], qf[ks][1], qf[ks][2], qf[ks][3], ad);
        }
    }
    __syncthreads();

    // ---- K/V prologue: tile 0 -> stage 0 (3 mats x 64 rows x 8 segs = 1536) ----
    #pragma unroll
    for (int i = 0; i < 6; i++) {
        int c = tid + i * 256;
        int mat = c >> 9, r = (c >> 3) & 63, seg = c & 7;
        uint32_t dst = sb + mat * A_KMAT + r * A_KSTRIDE + seg * 16;
        CP_ASYNC16(dst, srcs[mat] + (size_t)r * DK + seg * 8);
    }
    CP_COMMIT();

    float Oacc[8][4];
    #pragma unroll
    for (int j = 0; j < 8; j++)
        #pragma unroll
        for (int r = 0; r < 4; r++) Oacc[j][r] = 0.0f;
    float rowsum0 = 0.0f, rowsum1 = 0.0f;
    float m0 = -INFINITY, m1 = -INFINITY;

    const int row0 = q0 + warpM + (lane >> 2);
    const int dc = 2 * (lane & 3);

    for (int kt = 0; kt < 32; kt++) {
        // mask bits (gmem; overlap with wait)
        uint32_t mw0[2], mw1[2];
        #pragma unroll
        for (int w = 0; w < 2; w++) {
            mw0[w] = g_maskbits[(size_t)row0 * MASK_W + kt * 2 + w];
            mw1[w] = g_maskbits[(size_t)(row0 + 8) * MASK_W + kt * 2 + w];
        }

        CP_WAIT0();
        __syncthreads();
        if (kt + 1 < 32) {
            const int kbase = (kt + 1) * 64;
            const uint32_t stg = sb + ((kt + 1) & 1) * A_STAGE;
            #pragma unroll
            for (int i = 0; i < 6; i++) {
                int c = tid + i * 256;
                int mat = c >> 9, r = (c >> 3) & 63, seg = c & 7;
                uint32_t dst = stg + mat * A_KMAT + r * A_KSTRIDE + seg * 16;
                CP_ASYNC16(dst, srcs[mat] + (size_t)(kbase + r) * DK + seg * 8);
            }
            CP_COMMIT();
        }

        const uint32_t stg = sb + (kt & 1) * A_STAGE;

        // ---- S = Q K^T (fp16 2-pass: Qf x (Kh + Kl)) ----
        float Sacc[8][4];
        #pragma unroll
        for (int j = 0; j < 8; j++)
            #pragma unroll
            for (int r = 0; r < 4; r++) Sacc[j][r] = 0.0f;

        #pragma unroll
        for (int ks = 0; ks < 4; ks++) {
            const uint32_t kOffB = (ks * 16 + 8 * ((lane >> 3) & 1)) * 2;
            #pragma unroll
            for (int j = 0; j < 8; j += 2) {
                uint32_t bd = stg + ((j + (lane >> 4)) * 8 + (lane & 7)) * A_KSTRIDE + kOffB;
                uint32_t bh0, bh1, bh2, bh3, bl0, bl1, bl2, bl3;
                LDSM_X4(bh0, bh1, bh2, bh3, bd);
                LDSM_X4(bl0, bl1, bl2, bl3, bd + A_KMAT);
                mma_f16(Sacc[j], qf[ks][0], qf[ks][1], qf[ks][2], qf[ks][3], bh0, bh1);
                mma_f16(Sacc[j], qf[ks][0], qf[ks][1], qf[ks][2], qf[ks][3], bl0, bl1);
                mma_f16(Sacc[j + 1], qf[ks][0], qf[ks][1], qf[ks][2], qf[ks][3], bh2, bh3);
                mma_f16(Sacc[j + 1], qf[ks][0], qf[ks][1], qf[ks][2], qf[ks][3], bl2, bl3);
            }
        }

        // ---- apply mask (s -> -inf) + tile row max ----
        float tmax0 = -INFINITY, tmax1 = -INFINITY;
        #pragma unroll
        for (int j = 0; j < 8; j++) {
            const int sh = (j & 3) * 8 + dc;
            uint32_t b0 = (mw0[j >> 2] >> sh) & 3u;
            uint32_t b1 = (mw1[j >> 2] >> sh) & 3u;
            if (b0 & 1u) Sacc[j][0] = -INFINITY;
            if (b0 & 2u) Sacc[j][1] = -INFINITY;
            if (b1 & 1u) Sacc[j][2] = -INFINITY;
            if (b1 & 2u) Sacc[j][3] = -INFINITY;
            tmax0 = fmaxf(tmax0, fmaxf(Sacc[j][0], Sacc[j][1]));
            tmax1 = fmaxf(tmax1, fmaxf(Sacc[j][2], Sacc[j][3]));
        }
        tmax0 = fmaxf(tmax0, __shfl_xor_sync(0xFFFFFFFFu, tmax0, 1));
        tmax0 = fmaxf(tmax0, __shfl_xor_sync(0xFFFFFFFFu, tmax0, 2));
        tmax1 = fmaxf(tmax1, __shfl_xor_sync(0xFFFFFFFFu, tmax1, 1));
        tmax1 = fmaxf(tmax1, __shfl_xor_sync(0xFFFFFFFFu, tmax1, 2));
        if (tmax0 > m0) {
            float sc = __expf(m0 - tmax0);   // m0=-inf -> 0; Oacc/rowsum were 0
            rowsum0 *= sc;
            #pragma unroll
            for (int dj = 0; dj < 8; dj++) { Oacc[dj][0] *= sc; Oacc[dj][1] *= sc; }
            m0 = tmax0;
        }
        if (tmax1 > m1) {
            float sc = __expf(m1 - tmax1);
            rowsum1 *= sc;
            #pragma unroll
            for (int dj = 0; dj < 8; dj++) { Oacc[dj][2] *= sc; Oacc[dj][3] *= sc; }
            m1 = tmax1;
        }
        const float mm0 = (m0 == -INFINITY) ? 0.0f : m0;
        const float mm1 = (m1 == -INFINITY) ? 0.0f : m1;

        // ---- p = exp(s - m) in fp16, P·V (1-pass fp16, V single via trans) ----
        #pragma unroll
        for (int s = 0; s < 4; s++) {
            uint32_t pa[4];
            #pragma unroll
            for (int h2 = 0; h2 < 2; h2++) {
                const int j = 2 * s + h2;
                float p0 = __expf(Sacc[j][0] - mm0);   // masked: exp(-inf)=0
                float p1 = __expf(Sacc[j][1] - mm0);
                float p2 = __expf(Sacc[j][2] - mm1);
                float p3 = __expf(Sacc[j][3] - mm1);
                __half h0 = __float2half_rn(p0);
                __half h1 = __float2half_rn(p1);
                __half h2b = __float2half_rn(p2);
                __half h3 = __float2half_rn(p3);
                rowsum0 += __half2float(h0) + __half2float(h1);
                rowsum1 += __half2float(h2b) + __half2float(h3);
                pa[h2 * 2 + 0] = pack_h2(h0, h1);
                pa[h2 * 2 + 1] = pack_h2(h2b, h3);
            }
            // V fragments: rows = keys (s*16 + k), cols = d; trans-load
            const uint32_t vrow = (s * 16 + (lane & 7) + 8 * ((lane >> 3) & 1));
            #pragma unroll
            for (int dj = 0; dj < 8; dj += 2) {
                uint32_t vd = stg + A_VOFF + vrow * A_KSTRIDE + (dj * 8 + 8 * (lane >> 4)) * 2;
                uint32_t vh0, vh1, vh2, vh3;
                LDSM_X4_T(vh0, vh1, vh2, vh3, vd);
                mma_f16(Oacc[dj], pa[0], pa[1], pa[2], pa[3], vh0, vh1);
                mma_f16(Oacc[dj + 1], pa[0], pa[1], pa[2], pa[3], vh2, vh3);
            }
        }
    }

    // row-sum reduce across the 4 threads sharing a row
    rowsum0 += __shfl_xor_sync(0xFFFFFFFFu, rowsum0, 1);
    rowsum0 += __shfl_xor_sync(0xFFFFFFFFu, rowsum0, 2);
    rowsum1 += __shfl_xor_sync(0xFFFFFFFFu, rowsum1, 1);
    rowsum1 += __shfl_xor_sync(0xFFFFFFFFu, rowsum1, 2);
    const float inv0 = (rowsum0 > 0.0f) ? (1.0f / rowsum0) : 0.0f;
    const float inv1 = (rowsum1 > 0.0f) ? (1.0f / rowsum1) : 0.0f;

    const int b = bh >> 4, h = bh & 15;
    #pragma unroll
    for (int dj = 0; dj < 8; dj++) {
        int d = h * DK + dj * 8 + dc;
        {
            float v0 = Oacc[dj][0] * inv0, v1 = Oacc[dj][1] * inv0;
            size_t idx = ((size_t)(b * LL + row0)) * DMODEL + d;
            store_h2(&Cf[idx], __float2half_rn(v0), __float2half_rn(v1));
        }
        {
            float v0 = Oacc[dj][2] * inv1, v1 = Oacc[dj][3] * inv1;
            size_t idx = ((size_t)(b * LL + row0 + 8)) * DMODEL + d;
            store_h2(&Cf[idx], __float2half_rn(v0), __float2half_rn(v1));
        }
    }
}

// ---------------------------------------------------------------------------
// Launch
// ---------------------------------------------------------------------------
extern "C" void kernel_launch(void* const* d_in, const int* in_sizes, int n_in,
                              void* d_out, int out_size) {
    (void)in_sizes; (void)n_in; (void)out_size;
    const float* query = (const float*)d_in[0];
    const float* key   = (const float*)d_in[1];
    const float* value = (const float*)d_in[2];
    const void*  mask  = d_in[3];
    const float* W_q = (const float*)d_in[4];
    const float* b_q = (const float*)d_in[5];
    const float* W_k = (const float*)d_in[6];
    const float* b_k = (const float*)d_in[7];
    const float* W_v = (const float*)d_in[8];
    const float* b_v = (const float*)d_in[9];
    const float* W_o = (const float*)d_in[10];
    const float* b_o = (const float*)d_in[11];

    __half *in_q, *in_k, *in_v;
    __half *w_qh, *w_ql, *w_kh, *w_kl, *w_vh, *w_vl, *w_oh, *w_ol;
    __half *Qfp, *Kfhp, *Kflp, *Vfp, *Cfp;
    cudaGetSymbolAddress((void**)&in_q, g_in_q);
    cudaGetSymbolAddress((void**)&in_k, g_in_k);
    cudaGetSymbolAddress((void**)&in_v, g_in_v);
    cudaGetSymbolAddress((void**)&w_qh, g_w_qh);   cudaGetSymbolAddress((void**)&w_ql, g_w_ql);
    cudaGetSymbolAddress((void**)&w_kh, g_w_kh);   cudaGetSymbolAddress((void**)&w_kl, g_w_kl);
    cudaGetSymbolAddress((void**)&w_vh, g_w_vh);   cudaGetSymbolAddress((void**)&w_vl, g_w_vl);
    cudaGetSymbolAddress((void**)&w_oh, g_w_oh);   cudaGetSymbolAddress((void**)&w_ol, g_w_ol);
    cudaGetSymbolAddress((void**)&Qfp, g_Qf);
    cudaGetSymbolAddress((void**)&Kfhp, g_Kfh);    cudaGetSymbolAddress((void**)&Kflp, g_Kfl);
    cudaGetSymbolAddress((void**)&Vfp, g_Vf);
    cudaGetSymbolAddress((void**)&Cfp, g_Cf);

    cudaFuncSetAttribute(mma_gemm, cudaFuncAttributeMaxDynamicSharedMemorySize, GEMM_SMEM);
    cudaFuncSetAttribute(attn_mma, cudaFuncAttributeMaxDynamicSharedMemorySize, ATTN_SMEM);

    // Fused prep: mask bits + q/k/v fp16 convert + weight transpose/split
    PrepArgs pa;
    pa.mask = mask;
    pa.q = (const float4*)query; pa.k = (const float4*)key; pa.v = (const float4*)value;
    pa.oq = (__half2*)in_q; pa.ok = (__half2*)in_k; pa.ov = (__half2*)in_v;
    pa.wq = W_q; pa.wk = W_k; pa.wv = W_v; pa.wo = W_o;
    pa.wqh = w_qh; pa.wql = w_ql; pa.wkh = w_kh; pa.wkl = w_kl;
    pa.wvh = w_vh; pa.wvl = w_vl; pa.woh = w_oh; pa.wol = w_ol;
    prep_kernel<<<PREP_TOTAL, 256>>>(pa);

    // Fused Q/K/V projections: grid.z = 3
    // Q: 2-pass -> fp16 single. K: 2-pass -> fp16 hi/lo. V: 1-pass -> fp16 single.
    GArgs gp = {};
    gp.A[0] = in_q; gp.Bh[0] = w_qh; gp.Bl[0] = w_ql;
    gp.bias[0] = b_q; gp.ohf[0] = Qfp; gp.mode[0] = 3; gp.np[0] = 2;
    gp.A[1] = in_k; gp.Bh[1] = w_kh; gp.Bl[1] = w_kl;
    gp.bias[1] = b_k; gp.ohf[1] = Kfhp; gp.olf[1] = Kflp; gp.mode[1] = 2; gp.np[1] = 2;
    gp.A[2] = in_v; gp.Bh[2] = w_vh; gp.Bl[2] = w_vl;
    gp.bias[2] = b_v; gp.ohf[2] = Vfp; gp.mode[2] = 3; gp.np[2] = 1;
    dim3 gg3(DMODEL / 128, MROWS / 128, 3);   // (8, 32, 3)
    mma_gemm<<<gg3, 256, GEMM_SMEM>>>(gp);

    dim3 ag(LL / 128, BB * NH);               // (16, 32)
    attn_mma<<<ag, 256, ATTN_SMEM>>>(Qfp, Kfhp, Kflp, Vfp, Cfp);

    // Output projection (A = attention output in single fp16; 1-PASS W)
    GArgs go = {};
    go.A[0] = Cfp; go.Bh[0] = w_oh; go.Bl[0] = w_ol;
    go.bias[0] = b_o; go.outF[0] = (float*)d_out; go.mode[0] = 0; go.np[0] = 1;
    dim3 gg1(DMODEL / 128, MROWS / 128, 1);   // (8, 32, 1)
    mma_gemm<<<gg1, 256, GEMM_SMEM>>>(go);
}

// round 17
// speedup vs baseline: 1.4202x; 1.0452x over previous
#include <cuda_runtime.h>
#include <cuda_bf16.h>
#include <cuda_fp16.h>
#include <math.h>
#include <stdint.h>

// Problem constants
#define BB 2
#define LL 2048
#define DMODEL 1024
#define NH 16
#define DK 64
#define MROWS (BB * LL)          // 4096
#define MASK_W (LL / 32)         // 64 words per row
#define MASK_WORDS (LL * MASK_W)

// ---------------------------------------------------------------------------
// Device scratch (no allocations allowed)
// ---------------------------------------------------------------------------
__device__ __half g_in_q[MROWS * DMODEL], g_in_k[MROWS * DMODEL], g_in_v[MROWS * DMODEL];
__device__ __half g_w_qh[DMODEL * DMODEL], g_w_ql[DMODEL * DMODEL];
__device__ __half g_w_kh[DMODEL * DMODEL], g_w_kl[DMODEL * DMODEL];
__device__ __half g_w_vh[DMODEL * DMODEL], g_w_vl[DMODEL * DMODEL];
__device__ __half g_w_oh[DMODEL * DMODEL], g_w_ol[DMODEL * DMODEL];
__device__ __half g_Qf[MROWS * DMODEL];                                // [b,h,l,d] fp16 single
__device__ __half g_Kfh[MROWS * DMODEL], g_Kfl[MROWS * DMODEL];        // [b,h,l,d] fp16 hi/lo
__device__ __half g_Vf[MROWS * DMODEL];                                // [b,h,l,d] fp16 single
__device__ __half g_Cf[MROWS * DMODEL];                                // [b,l,dmodel] fp16
__device__ unsigned int g_maskbits[MASK_WORDS];

// ---------------------------------------------------------------------------
// PTX helpers (portable PTX only: mma.sync / ldmatrix / cp.async)
// ---------------------------------------------------------------------------
__device__ __forceinline__ uint32_t smem_u32(const void* p) {
    uint32_t a;
    asm("{ .reg .u64 t; cvta.to.shared.u64 t, %1; cvt.u32.u64 %0, t; }" : "=r"(a) : "l"(p));
    return a;
}

#define CP_ASYNC16(dst, src) \
    asm volatile("cp.async.cg.shared.global [%0], [%1], 16;" :: "r"(dst), "l"(src))
#define CP_COMMIT() asm volatile("cp.async.commit_group;" ::: "memory")
#define CP_WAIT0()  asm volatile("cp.async.wait_group 0;" ::: "memory")

#define LDSM_X4(r0, r1, r2, r3, addr) \
    asm volatile("ldmatrix.sync.aligned.m8n8.x4.shared.b16 {%0,%1,%2,%3}, [%4];" \
        : "=r"(r0), "=r"(r1), "=r"(r2), "=r"(r3) : "r"(addr))
#define LDSM_X4_T(r0, r1, r2, r3, addr) \
    asm volatile("ldmatrix.sync.aligned.m8n8.x4.trans.shared.b16 {%0,%1,%2,%3}, [%4];" \
        : "=r"(r0), "=r"(r1), "=r"(r2), "=r"(r3) : "r"(addr))

__device__ __forceinline__ void mma_f16(float* c, uint32_t a0, uint32_t a1, uint32_t a2, uint32_t a3,
                                        uint32_t b0, uint32_t b1) {
    asm volatile("mma.sync.aligned.m16n8k16.row.col.f32.f16.f16.f32 "
        "{%0,%1,%2,%3}, {%4,%5,%6,%7}, {%8,%9}, {%0,%1,%2,%3};"
        : "+f"(c[0]), "+f"(c[1]), "+f"(c[2]), "+f"(c[3])
        : "r"(a0), "r"(a1), "r"(a2), "r"(a3), "r"(b0), "r"(b1));
}

__device__ __forceinline__ void split2h(float x, __half& h, __half& l) {
    h = __float2half_rn(x);
    l = __float2half_rn(x - __half2float(h));
}
__device__ __forceinline__ uint32_t pack_h2(__half e0, __half e1) {
    __half2 t; t.x = e0; t.y = e1;
    return *(uint32_t*)&t;
}
__device__ __forceinline__ void store_h2(__half* p, __half e0, __half e1) {
    __half2 t; t.x = e0; t.y = e1;
    *(__half2*)p = t;
}

// ---------------------------------------------------------------------------
// Fused prep kernel: blockIdx.x ranges select mask / conv3 / transpose work.
// ---------------------------------------------------------------------------
#define PREP_MASK_CTAS 512
#define PREP_CONV_CTAS 4096
#define PREP_TR_CTAS   1024
#define PREP_TOTAL (PREP_MASK_CTAS + 3 * PREP_CONV_CTAS + 4 * PREP_TR_CTAS)

struct PrepArgs {
    const void* mask;
    const float4 *q, *k, *v;
    __half2 *oq, *ok, *ov;
    const float *wq, *wk, *wv, *wo;
    __half *wqh, *wql, *wkh, *wkl, *wvh, *wvl, *woh, *wol;
};

__global__ __launch_bounds__(256) void prep_kernel(PrepArgs pa) {
    const int cta = blockIdx.x, tid = threadIdx.x;
    if (cta < PREP_MASK_CTAS) {
        const unsigned int* w = (const unsigned int*)pa.mask;
        bool all_i32 = true, all_f32 = true;
        #pragma unroll
        for (int i = 0; i < 64; i++) {
            unsigned int v = w[i];
            if (v > 1u) all_i32 = false;
            if (v != 0u && v != 0x3F800000u) all_f32 = false;
        }
        int idx = cta * 256 + tid;
        size_t base = (size_t)idx * 32;
        uint32_t bits = 0;
        if (all_i32 || all_f32) {
            const uint4* p = (const uint4*)((const unsigned int*)pa.mask + base);
            #pragma unroll
            for (int g = 0; g < 8; g++) {
                uint4 v = p[g];
                bits |= (v.x != 0u ? 1u : 0u) << (g * 4 + 0);
                bits |= (v.y != 0u ? 1u : 0u) << (g * 4 + 1);
                bits |= (v.z != 0u ? 1u : 0u) << (g * 4 + 2);
                bits |= (v.w != 0u ? 1u : 0u) << (g * 4 + 3);
            }
        } else {
            const uchar4* p = (const uchar4*)((const unsigned char*)pa.mask + base);
            #pragma unroll
            for (int g = 0; g < 8; g++) {
                uchar4 v = p[g];
                bits |= (v.x ? 1u : 0u) << (g * 4 + 0);
                bits |= (v.y ? 1u : 0u) << (g * 4 + 1);
                bits |= (v.z ? 1u : 0u) << (g * 4 + 2);
                bits |= (v.w ? 1u : 0u) << (g * 4 + 3);
            }
        }
        g_maskbits[idx] = bits;
    } else if (cta < PREP_MASK_CTAS + 3 * PREP_CONV_CTAS) {
        int rel = cta - PREP_MASK_CTAS;
        int which = rel / PREP_CONV_CTAS, blk = rel % PREP_CONV_CTAS;
        const float4* in = (which == 0) ? pa.q : (which == 1) ? pa.k : pa.v;
        __half2* out = (which == 0) ? pa.oq : (which == 1) ? pa.ok : pa.ov;
        int i = blk * 256 + tid;
        float4 vv = in[i];
        __half2 a, b;
        a.x = __float2half_rn(vv.x); a.y = __float2half_rn(vv.y);
        b.x = __float2half_rn(vv.z); b.y = __float2half_rn(vv.w);
        out[i * 2] = a;
        out[i * 2 + 1] = b;
    } else {
        int rel = cta - PREP_MASK_CTAS - 3 * PREP_CONV_CTAS;
        int which = rel / PREP_TR_CTAS, tile = rel % PREP_TR_CTAS;
        const float* in = (which == 0) ? pa.wq : (which == 1) ? pa.wk : (which == 2) ? pa.wv : pa.wo;
        __half* hi = (which == 0) ? pa.wqh : (which == 1) ? pa.wkh : (which == 2) ? pa.wvh : pa.woh;
        __half* lo = (which == 0) ? pa.wql : (which == 1) ? pa.wkl : (which == 2) ? pa.wvl : pa.wol;
        __shared__ float t[32][33];
        int n0 = (tile & 31) * 32, k0 = (tile >> 5) * 32;
        int c = tid & 31, r0 = tid >> 5;
        #pragma unroll
        for (int p = 0; p < 4; p++) {
            int r = r0 + p * 8;
            t[r][c] = in[(size_t)(k0 + r) * DMODEL + n0 + c];
        }
        __syncthreads();
        #pragma unroll
        for (int p = 0; p < 4; p++) {
            int r = r0 + p * 8;
            float v = t[c][r];
            int n = n0 + r, k = k0 + c;
            __half h, l;
            split2h(v, h, l);
            hi[(size_t)n * DMODEL + k] = h;
            lo[(size_t)n * DMODEL + k] = l;
        }
    }
}

// ---------------------------------------------------------------------------
// GEMM (fp16): C[m][n] = sum_k A[m,k]*W[n,k] + bias[n]
// np=2: W = Wh + Wl (2-pass). np=1: W = Wh only (1-pass).
// BK=64 (16 K-iterations): halves per-iter overhead vs BK=32.
// mode 0: fp32 out; 2: fp16 hi/lo [b,h,l,d]; 3: fp16 single [b,h,l,d].
// ---------------------------------------------------------------------------
#define G_STRIDE 144            // 64 fp16 + 16B pad
#define G_MAT    18432          // 128*144
#define G_STAGE  55296          // 3 mats
#define GEMM_SMEM (2 * G_STAGE) // 110592

struct GArgs {
    const __half *A[3], *Bh[3], *Bl[3];
    const float* bias[3];
    float* outF[3];
    __half *ohf[3], *olf[3];
    int mode[3];
    int np[3];
};

__global__ __launch_bounds__(256, 2) void mma_gemm(GArgs ga)
{
    extern __shared__ char smem[];
    const uint32_t sb = smem_u32(smem);
    const int z = blockIdx.z;
    const __half* __restrict__ A  = ga.A[z];
    const __half* __restrict__ Bh = ga.Bh[z];
    const __half* __restrict__ Bl = ga.Bl[z];
    const float* __restrict__ bias = ga.bias[z];
    const int mode = ga.mode[z];
    const int np = ga.np[z];

    const int tid = threadIdx.x, wid = tid >> 5, lane = tid & 31;
    const int bm = blockIdx.y * 128, bn = blockIdx.x * 128;
    const int warpM = (wid >> 2) * 64, warpN = (wid & 3) * 32;

    float acc[4][4][4];
    #pragma unroll
    for (int i = 0; i < 4; i++)
        #pragma unroll
        for (int j = 0; j < 4; j++)
            #pragma unroll
            for (int r = 0; r < 4; r++) acc[i][j][r] = 0.0f;

    const __half* srcs[3] = {A, Bh, Bl};

    // prologue: tile 0 -> stage 0 (3 mats x 128 rows x 8 segs = 3072 chunks)
    #pragma unroll
    for (int i = 0; i < 12; i++) {
        int c = tid + i * 256;
        int mat = c >> 10, r = (c >> 3) & 127, seg = c & 7;
        if (mat != 2 || np == 2) {
            uint32_t dst = sb + mat * G_MAT + r * G_STRIDE + seg * 16;
            int row = (mat < 1) ? (bm + r) : (bn + r);
            CP_ASYNC16(dst, srcs[mat] + (size_t)row * DMODEL + seg * 8);
        }
    }
    CP_COMMIT();

    for (int it = 0; it < 16; it++) {
        CP_WAIT0();
        __syncthreads();
        if (it + 1 < 16) {
            const int k0 = (it + 1) * 64;
            const uint32_t stg = sb + ((it + 1) & 1) * G_STAGE;
            #pragma unroll
            for (int i = 0; i < 12; i++) {
                int c = tid + i * 256;
                int mat = c >> 10, r = (c >> 3) & 127, seg = c & 7;
                if (mat != 2 || np == 2) {
                    uint32_t dst = stg + mat * G_MAT + r * G_STRIDE + seg * 16;
                    int row = (mat < 1) ? (bm + r) : (bn + r);
                    CP_ASYNC16(dst, srcs[mat] + (size_t)row * DMODEL + k0 + seg * 8);
                }
            }
            CP_COMMIT();
        }

        const uint32_t stg = sb + (it & 1) * G_STAGE;
        const uint32_t aRow = warpM + (lane & 15);
        #pragma unroll
        for (int ks = 0; ks < 4; ks++) {
            const uint32_t kOffA = (ks * 16 + 8 * (lane >> 4)) * 2;
            const uint32_t kOffB = (ks * 16 + 8 * ((lane >> 3) & 1)) * 2;
            uint32_t ah[4][4];
            #pragma unroll
            for (int mi = 0; mi < 4; mi++) {
                uint32_t ad = stg + (aRow + mi * 16) * G_STRIDE + kOffA;
                LDSM_X4(ah[mi][0], ah[mi][1], ah[mi][2], ah[mi][3], ad);
            }
            #pragma unroll
            for (int nj = 0; nj < 4; nj += 2) {
                uint32_t bd = stg + G_MAT
                            + (warpN + (nj + (lane >> 4)) * 8 + (lane & 7)) * G_STRIDE + kOffB;
                uint32_t bh0, bh1, bh2, bh3;
                LDSM_X4(bh0, bh1, bh2, bh3, bd);
                #pragma unroll
                for (int mi = 0; mi < 4; mi++) {
                    mma_f16(acc[mi][nj], ah[mi][0], ah[mi][1], ah[mi][2], ah[mi][3], bh0, bh1);
                    mma_f16(acc[mi][nj + 1], ah[mi][0], ah[mi][1], ah[mi][2], ah[mi][3], bh2, bh3);
                }
                if (np == 2) {
                    uint32_t bl0, bl1, bl2, bl3;
                    LDSM_X4(bl0, bl1, bl2, bl3, bd + G_MAT);
                    #pragma unroll
                    for (int mi = 0; mi < 4; mi++) {
                        mma_f16(acc[mi][nj], ah[mi][0], ah[mi][1], ah[mi][2], ah[mi][3], bl0, bl1);
                        mma_f16(acc[mi][nj + 1], ah[mi][0], ah[mi][1], ah[mi][2], ah[mi][3], bl2, bl3);
                    }
                }
            }
        }
    }

    // epilogue
    #pragma unroll
    for (int mi = 0; mi < 4; mi++) {
        #pragma unroll
        for (int nj = 0; nj < 4; nj++) {
            int n = bn + warpN + nj * 8 + 2 * (lane & 3);
            float bias0 = bias[n], bias1 = bias[n + 1];
            #pragma unroll
            for (int half = 0; half < 2; half++) {
                int m = bm + warpM + mi * 16 + (lane >> 2) + half * 8;
                float v0 = acc[mi][nj][half * 2 + 0] + bias0;
                float v1 = acc[mi][nj][half * 2 + 1] + bias1;
                if (mode == 0) {
                    float2 o; o.x = v0; o.y = v1;
                    *(float2*)&ga.outF[z][(size_t)m * DMODEL + n] = o;
                } else {
                    int b = m >> 11, l = m & 2047;
                    int h = n >> 6, d = n & 63;
                    size_t idx = (((size_t)(b * NH + h)) * LL + l) * DK + d;
                    if (mode == 2) {
                        __half h0, h1, l0, l1;
                        split2h(v0, h0, l0); split2h(v1, h1, l1);
                        store_h2(&ga.ohf[z][idx], h0, h1);
                        store_h2(&ga.olf[z][idx], l0, l1);
                    } else {
                        store_h2(&ga.ohf[z][idx], __float2half_rn(v0), __float2half_rn(v1));
                    }
                }
            }
        }
    }
}

// ---------------------------------------------------------------------------
// Flash attention, ONLINE softmax, 2-stage cp.async.
// CTA: 128 queries x one (b,h); 32 key tiles of 64; 8 warps, warp = 16 queries.
// S = fp16 2-PASS: Q single fp16 x K fp16 hi/lo (64 MMAs/tile).
// P = single fp16 (p = exp(s - m) <= 1). P·V = fp16 1-pass (32 MMAs/tile).
// ---------------------------------------------------------------------------
#define A_KSTRIDE 144           // 64 elems * 2B + 16 pad
#define A_KMAT    9216          // 64*144
#define A_VOFF    18432         // 2*A_KMAT (V single follows K hi/lo)
#define A_STAGE   27648         // 3 mats * 9216
#define ATTN_SMEM (2 * A_STAGE) // 55296

__global__ __launch_bounds__(256, 2) void attn_mma(
    const __half* __restrict__ Qf,
    const __half* __restrict__ Kfh, const __half* __restrict__ Kfl,
    const __half* __restrict__ Vf,
    __half* __restrict__ Cf)
{
    extern __shared__ char smem[];
    const uint32_t sb = smem_u32(smem);
    const int tid = threadIdx.x, wid = tid >> 5, lane = tid & 31;
    const int bh = blockIdx.y, q0 = blockIdx.x * 128;
    const int warpM = wid * 16;

    const __half* qbf = Qf + (size_t)bh * LL * DK;
    const __half* srcs[3] = {
        Kfh + (size_t)bh * LL * DK, Kfl + (size_t)bh * LL * DK,
        Vf + (size_t)bh * LL * DK};

    // ---- Q preload (single fp16): 128 rows x 8 segs = 1024 chunks ----
    #pragma unroll
    for (int i = 0; i < 4; i++) {
        int c = tid + i * 256;
        int r = c >> 3, seg = c & 7;
        const __half* src = qbf + (size_t)(q0 + r) * DK + seg * 8;
        *(uint4*)(smem + r * A_KSTRIDE + seg * 16) = *(const uint4*)src;
    }
    __syncthreads();
    uint32_t qf[4][4];
    {
        const uint32_t aRow = warpM + (lane & 15);
        #pragma unroll
        for (int ks = 0; ks < 4; ks++) {
            uint32_t ad = sb + aRow * A_KSTRIDE + (ks * 16 + 8 * (lane >> 4)) * 2;
            LDSM_X4(qf[ks][0], qf[ks][1], qf[ks][2], qf[ks][3], ad);
        }
    }
    __syncthreads();

    // ---- K/V prologue: tile 0 -> stage 0 (3 mats x 64 rows x 8 segs = 1536) ----
    #pragma unroll
    for (int i = 0; i < 6; i++) {
        int c = tid + i * 256;
        int mat = c >> 9, r = (c >> 3) & 63, seg = c & 7;
        uint32_t dst = sb + mat * A_KMAT + r * A_KSTRIDE + seg * 16;
        CP_ASYNC16(dst, srcs[mat] + (size_t)r * DK + seg * 8);
    }
    CP_COMMIT();

    float Oacc[8][4];
    #pragma unroll
    for (int j = 0; j < 8; j++)
        #pragma unroll
        for (int r = 0; r < 4; r++) Oacc[j][r] = 0.0f;
    float rowsum0 = 0.0f, rowsum1 = 0.0f;
    float m0 = -INFINITY, m1 = -INFINITY;

    const int row0 = q0 + warpM + (lane >> 2);
    const int dc = 2 * (lane & 3);

    for (int kt = 0; kt < 32; kt++) {
        // mask bits (gmem; overlap with wait)
        uint32_t mw0[2], mw1[2];
        #pragma unroll
        for (int w = 0; w < 2; w++) {
            mw0[w] = g_maskbits[(size_t)row0 * MASK_W + kt * 2 + w];
            mw1[w] = g_maskbits[(size_t)(row0 + 8) * MASK_W + kt * 2 + w];
        }

        CP_WAIT0();
        __syncthreads();
        if (kt + 1 < 32) {
            const int kbase = (kt + 1) * 64;
            const uint32_t stg = sb + ((kt + 1) & 1) * A_STAGE;
            #pragma unroll
            for (int i = 0; i < 6; i++) {
                int c = tid + i * 256;
                int mat = c >> 9, r = (c >> 3) & 63, seg = c & 7;
                uint32_t dst = stg + mat * A_KMAT + r * A_KSTRIDE + seg * 16;
                CP_ASYNC16(dst, srcs[mat] + (size_t)(kbase + r) * DK + seg * 8);
            }
            CP_COMMIT();
        }

        const uint32_t stg = sb + (kt & 1) * A_STAGE;

        // ---- S = Q K^T (fp16 2-pass: Qf x (Kh + Kl)) ----
        float Sacc[8][4];
        #pragma unroll
        for (int j = 0; j < 8; j++)
            #pragma unroll
            for (int r = 0; r < 4; r++) Sacc[j][r] = 0.0f;

        #pragma unroll
        for (int ks = 0; ks < 4; ks++) {
            const uint32_t kOffB = (ks * 16 + 8 * ((lane >> 3) & 1)) * 2;
            #pragma unroll
            for (int j = 0; j < 8; j += 2) {
                uint32_t bd = stg + ((j + (lane >> 4)) * 8 + (lane & 7)) * A_KSTRIDE + kOffB;
                uint32_t bh0, bh1, bh2, bh3, bl0, bl1, bl2, bl3;
                LDSM_X4(bh0, bh1, bh2, bh3, bd);
                LDSM_X4(bl0, bl1, bl2, bl3, bd + A_KMAT);
                mma_f16(Sacc[j], qf[ks][0], qf[ks][1], qf[ks][2], qf[ks][3], bh0, bh1);
                mma_f16(Sacc[j], qf[ks][0], qf[ks][1], qf[ks][2], qf[ks][3], bl0, bl1);
                mma_f16(Sacc[j + 1], qf[ks][0], qf[ks][1], qf[ks][2], qf[ks][3], bh2, bh3);
                mma_f16(Sacc[j + 1], qf[ks][0], qf[ks][1], qf[ks][2], qf[ks][3], bl2, bl3);
            }
        }

        // ---- apply mask (s -> -inf) + tile row max ----
        float tmax0 = -INFINITY, tmax1 = -INFINITY;
        #pragma unroll
        for (int j = 0; j < 8; j++) {
            const int sh = (j & 3) * 8 + dc;
            uint32_t b0 = (mw0[j >> 2] >> sh) & 3u;
            uint32_t b1 = (mw1[j >> 2] >> sh) & 3u;
            if (b0 & 1u) Sacc[j][0] = -INFINITY;
            if (b0 & 2u) Sacc[j][1] = -INFINITY;
            if (b1 & 1u) Sacc[j][2] = -INFINITY;
            if (b1 & 2u) Sacc[j][3] = -INFINITY;
            tmax0 = fmaxf(tmax0, fmaxf(Sacc[j][0], Sacc[j][1]));
            tmax1 = fmaxf(tmax1, fmaxf(Sacc[j][2], Sacc[j][3]));
        }
        tmax0 = fmaxf(tmax0, __shfl_xor_sync(0xFFFFFFFFu, tmax0, 1));
        tmax0 = fmaxf(tmax0, __shfl_xor_sync(0xFFFFFFFFu, tmax0, 2));
        tmax1 = fmaxf(tmax1, __shfl_xor_sync(0xFFFFFFFFu, tmax1, 1));
        tmax1 = fmaxf(tmax1, __shfl_xor_sync(0xFFFFFFFFu, tmax1, 2));
        if (tmax0 > m0) {
            float sc = __expf(m0 - tmax0);   // m0=-inf -> 0; Oacc/rowsum were 0
            rowsum0 *= sc;
            #pragma unroll
            for (int dj = 0; dj < 8; dj++) { Oacc[dj][0] *= sc; Oacc[dj][1] *= sc; }
            m0 = tmax0;
        }
        if (tmax1 > m1) {
            float sc = __expf(m1 - tmax1);
            rowsum1 *= sc;
            #pragma unroll
            for (int dj = 0; dj < 8; dj++) { Oacc[dj][2] *= sc; Oacc[dj][3] *= sc; }
            m1 = tmax1;
        }
        const float mm0 = (m0 == -INFINITY) ? 0.0f : m0;
        const float mm1 = (m1 == -INFINITY) ? 0.0f : m1;

        // ---- p = exp(s - m) in fp16, P·V (1-pass fp16, V single via trans) ----
        #pragma unroll
        for (int s = 0; s < 4; s++) {
            uint32_t pa[4];
            #pragma unroll
            for (int h2 = 0; h2 < 2; h2++) {
                const int j = 2 * s + h2;
                float p0 = __expf(Sacc[j][0] - mm0);   // masked: exp(-inf)=0
                float p1 = __expf(Sacc[j][1] - mm0);
                float p2 = __expf(Sacc[j][2] - mm1);
                float p3 = __expf(Sacc[j][3] - mm1);
                __half h0 = __float2half_rn(p0);
                __half h1 = __float2half_rn(p1);
                __half h2b = __float2half_rn(p2);
                __half h3 = __float2half_rn(p3);
                rowsum0 += __half2float(h0) + __half2float(h1);
                rowsum1 += __half2float(h2b) + __half2float(h3);
                pa[h2 * 2 + 0] = pack_h2(h0, h1);
                pa[h2 * 2 + 1] = pack_h2(h2b, h3);
            }
            // V fragments: rows = keys (s*16 + k), cols = d; trans-load
            const uint32_t vrow = (s * 16 + (lane & 7) + 8 * ((lane >> 3) & 1));
            #pragma unroll
            for (int dj = 0; dj < 8; dj += 2) {
                uint32_t vd = stg + A_VOFF + vrow * A_KSTRIDE + (dj * 8 + 8 * (lane >> 4)) * 2;
                uint32_t vh0, vh1, vh2, vh3;
                LDSM_X4_T(vh0, vh1, vh2, vh3, vd);
                mma_f16(Oacc[dj], pa[0], pa[1], pa[2], pa[3], vh0, vh1);
                mma_f16(Oacc[dj + 1], pa[0], pa[1], pa[2], pa[3], vh2, vh3);
            }
        }
    }

    // row-sum reduce across the 4 threads sharing a row
    rowsum0 += __shfl_xor_sync(0xFFFFFFFFu, rowsum0, 1);
    rowsum0 += __shfl_xor_sync(0xFFFFFFFFu, rowsum0, 2);
    rowsum1 += __shfl_xor_sync(0xFFFFFFFFu, rowsum1, 1);
    rowsum1 += __shfl_xor_sync(0xFFFFFFFFu, rowsum1, 2);
    const float inv0 = (rowsum0 > 0.0f) ? (1.0f / rowsum0) : 0.0f;
    const float inv1 = (rowsum1 > 0.0f) ? (1.0f / rowsum1) : 0.0f;

    const int b = bh >> 4, h = bh & 15;
    #pragma unroll
    for (int dj = 0; dj < 8; dj++) {
        int d = h * DK + dj * 8 + dc;
        {
            float v0 = Oacc[dj][0] * inv0, v1 = Oacc[dj][1] * inv0;
            size_t idx = ((size_t)(b * LL + row0)) * DMODEL + d;
            store_h2(&Cf[idx], __float2half_rn(v0), __float2half_rn(v1));
        }
        {
            float v0 = Oacc[dj][2] * inv1, v1 = Oacc[dj][3] * inv1;
            size_t idx = ((size_t)(b * LL + row0 + 8)) * DMODEL + d;
            store_h2(&Cf[idx], __float2half_rn(v0), __float2half_rn(v1));
        }
    }
}

// ---------------------------------------------------------------------------
// Launch
// ---------------------------------------------------------------------------
extern "C" void kernel_launch(void* const* d_in, const int* in_sizes, int n_in,
                              void* d_out, int out_size) {
    (void)in_sizes; (void)n_in; (void)out_size;
    const float* query = (const float*)d_in[0];
    const float* key   = (const float*)d_in[1];
    const float* value = (const float*)d_in[2];
    const void*  mask  = d_in[3];
    const float* W_q = (const float*)d_in[4];
    const float* b_q = (const float*)d_in[5];
    const float* W_k = (const float*)d_in[6];
    const float* b_k = (const float*)d_in[7];
    const float* W_v = (const float*)d_in[8];
    const float* b_v = (const float*)d_in[9];
    const float* W_o = (const float*)d_in[10];
    const float* b_o = (const float*)d_in[11];

    __half *in_q, *in_k, *in_v;
    __half *w_qh, *w_ql, *w_kh, *w_kl, *w_vh, *w_vl, *w_oh, *w_ol;
    __half *Qfp, *Kfhp, *Kflp, *Vfp, *Cfp;
    cudaGetSymbolAddress((void**)&in_q, g_in_q);
    cudaGetSymbolAddress((void**)&in_k, g_in_k);
    cudaGetSymbolAddress((void**)&in_v, g_in_v);
    cudaGetSymbolAddress((void**)&w_qh, g_w_qh);   cudaGetSymbolAddress((void**)&w_ql, g_w_ql);
    cudaGetSymbolAddress((void**)&w_kh, g_w_kh);   cudaGetSymbolAddress((void**)&w_kl, g_w_kl);
    cudaGetSymbolAddress((void**)&w_vh, g_w_vh);   cudaGetSymbolAddress((void**)&w_vl, g_w_vl);
    cudaGetSymbolAddress((void**)&w_oh, g_w_oh);   cudaGetSymbolAddress((void**)&w_ol, g_w_ol);
    cudaGetSymbolAddress((void**)&Qfp, g_Qf);
    cudaGetSymbolAddress((void**)&Kfhp, g_Kfh);    cudaGetSymbolAddress((void**)&Kflp, g_Kfl);
    cudaGetSymbolAddress((void**)&Vfp, g_Vf);
    cudaGetSymbolAddress((void**)&Cfp, g_Cf);

    cudaFuncSetAttribute(mma_gemm, cudaFuncAttributeMaxDynamicSharedMemorySize, GEMM_SMEM);
    cudaFuncSetAttribute(attn_mma, cudaFuncAttributeMaxDynamicSharedMemorySize, ATTN_SMEM);

    // Fused prep: mask bits + q/k/v fp16 convert + weight transpose/split
    PrepArgs pa;
    pa.mask = mask;
    pa.q = (const float4*)query; pa.k = (const float4*)key; pa.v = (const float4*)value;
    pa.oq = (__half2*)in_q; pa.ok = (__half2*)in_k; pa.ov = (__half2*)in_v;
    pa.wq = W_q; pa.wk = W_k; pa.wv = W_v; pa.wo = W_o;
    pa.wqh = w_qh; pa.wql = w_ql; pa.wkh = w_kh; pa.wkl = w_kl;
    pa.wvh = w_vh; pa.wvl = w_vl; pa.woh = w_oh; pa.wol = w_ol;
    prep_kernel<<<PREP_TOTAL, 256>>>(pa);

    // Fused Q/K/V projections: grid.z = 3
    // Q: 2-pass -> fp16 single. K: 2-pass -> fp16 hi/lo. V: 1-pass -> fp16 single.
    GArgs gp = {};
    gp.A[0] = in_q; gp.Bh[0] = w_qh; gp.Bl[0] = w_ql;
    gp.bias[0] = b_q; gp.ohf[0] = Qfp; gp.mode[0] = 3; gp.np[0] = 2;
    gp.A[1] = in_k; gp.Bh[1] = w_kh; gp.Bl[1] = w_kl;
    gp.bias[1] = b_k; gp.ohf[1] = Kfhp; gp.olf[1] = Kflp; gp.mode[1] = 2; gp.np[1] = 2;
    gp.A[2] = in_v; gp.Bh[2] = w_vh; gp.Bl[2] = w_vl;
    gp.bias[2] = b_v; gp.ohf[2] = Vfp; gp.mode[2] = 3; gp.np[2] = 1;
    dim3 gg3(DMODEL / 128, MROWS / 128, 3);   // (8, 32, 3)
    mma_gemm<<<gg3, 256, GEMM_SMEM>>>(gp);

    dim3 ag(LL / 128, BB * NH);               // (16, 32)
    attn_mma<<<ag, 256, ATTN_SMEM>>>(Qfp, Kfhp, Kflp, Vfp, Cfp);

    // Output projection (A = attention output in single fp16; 1-PASS W)
    GArgs go = {};
    go.A[0] = Cfp; go.Bh[0] = w_oh; go.Bl[0] = w_ol;
    go.bias[0] = b_o; go.outF[0] = (float*)d_out; go.mode[0] = 0; go.np[0] = 1;
    dim3 gg1(DMODEL / 128, MROWS / 128, 1);   // (8, 32, 1)
    mma_gemm<<<gg1, 256, GEMM_SMEM>>>(go);
}